// round 1
// baseline (speedup 1.0000x reference)
#include <cuda_runtime.h>
#include <cstddef>

// Problem constants
#define BQ 4
#define SEQ 1024
#define DEMB 1024
#define NHEAD 16
#define DRED 64
#define NTOK (BQ*SEQ)          // 4096
#define DFFN (4*DEMB)          // 4096

// ---------------------------------------------------------------------------
// Scratch (static device memory; no allocations anywhere)
// ---------------------------------------------------------------------------
__device__ float g_q  [(size_t)BQ*NHEAD*SEQ*DRED];   // 4M
__device__ float g_k  [(size_t)BQ*NHEAD*SEQ*DRED];   // 4M
__device__ float g_v  [(size_t)BQ*NHEAD*SEQ*DRED];   // 4M
__device__ float g_att[(size_t)NTOK*DEMB];           // 4M   [tok, h*64+r]
__device__ float g_res[(size_t)NTOK*DEMB];           // 4M
__device__ float g_ln1[(size_t)NTOK*DEMB];           // 4M
__device__ float g_ln2[(size_t)NTOK*DEMB];           // 4M
__device__ float g_ffn[(size_t)NTOK*DFFN];           // 16M

// ---------------------------------------------------------------------------
// Generic SGEMM:  C[M,N] = A[M,K] * B + (bias) + (resid), optional relu.
//  BMODE: 0 = B row-major [K,N];  1 = B is w[h, k, r] with n = h*64 + r
//  OMODE: 0 = C row-major [M,N];  1 = C in [B,H,S,R] layout (m=b*S+s, n=h*64+r)
// Tiles: 128x128x8, 256 threads, 8x8 micro (split 4+4 to avoid bank conflicts)
// ---------------------------------------------------------------------------
template<int BMODE, int OMODE, bool BIAS, bool RESID, bool RELU>
__global__ __launch_bounds__(256)
void sgemm(const float* __restrict__ A, const float* __restrict__ B,
           const float* __restrict__ bias, const float* __restrict__ resid,
           float* __restrict__ C, int M, int N, int K)
{
    __shared__ float As[8][128];
    __shared__ float Bs[8][128];

    const int t  = threadIdx.x;
    const int tx = t & 15;
    const int ty = t >> 4;
    const int m0 = blockIdx.y * 128;
    const int n0 = blockIdx.x * 128;

    const int arow = t >> 1;          // 0..127
    const int acol = (t & 1) * 4;     // 0 or 4
    const int brow = t >> 5;          // 0..7
    const int bcol = (t & 31) * 4;    // 0..124

    float acc[8][8];
    #pragma unroll
    for (int i = 0; i < 8; i++)
        #pragma unroll
        for (int j = 0; j < 8; j++) acc[i][j] = 0.f;

    for (int k0 = 0; k0 < K; k0 += 8) {
        // A tile 128x8, stored transposed
        float4 av = *(const float4*)&A[(size_t)(m0 + arow) * K + k0 + acol];
        As[acol + 0][arow] = av.x;
        As[acol + 1][arow] = av.y;
        As[acol + 2][arow] = av.z;
        As[acol + 3][arow] = av.w;
        // B tile 8x128
        float4 bv;
        if (BMODE == 0) {
            bv = *(const float4*)&B[(size_t)(k0 + brow) * N + n0 + bcol];
        } else {
            int n = n0 + bcol;
            bv = *(const float4*)&B[(size_t)(n >> 6) * K * 64
                                    + (size_t)(k0 + brow) * 64 + (n & 63)];
        }
        *(float4*)&Bs[brow][bcol] = bv;
        __syncthreads();

        #pragma unroll
        for (int k = 0; k < 8; k++) {
            float a[8], bb[8];
            *(float4*)&a[0]  = *(const float4*)&As[k][ty * 4];
            *(float4*)&a[4]  = *(const float4*)&As[k][64 + ty * 4];
            *(float4*)&bb[0] = *(const float4*)&Bs[k][tx * 4];
            *(float4*)&bb[4] = *(const float4*)&Bs[k][64 + tx * 4];
            #pragma unroll
            for (int i = 0; i < 8; i++)
                #pragma unroll
                for (int j = 0; j < 8; j++)
                    acc[i][j] += a[i] * bb[j];
        }
        __syncthreads();
    }

    // Epilogue
    #pragma unroll
    for (int ii = 0; ii < 8; ii++) {
        int mi = m0 + ((ii < 4) ? (ty * 4 + ii) : (64 + ty * 4 + ii - 4));
        #pragma unroll
        for (int jc = 0; jc < 2; jc++) {
            int nj = n0 + ((jc == 0) ? (tx * 4) : (64 + tx * 4));
            float4 r;
            r.x = acc[ii][jc * 4 + 0];
            r.y = acc[ii][jc * 4 + 1];
            r.z = acc[ii][jc * 4 + 2];
            r.w = acc[ii][jc * 4 + 3];
            if (BIAS) {
                float4 b4 = *(const float4*)&bias[nj];
                r.x += b4.x; r.y += b4.y; r.z += b4.z; r.w += b4.w;
            }
            if (RESID) {
                float4 q4 = *(const float4*)&resid[(size_t)mi * N + nj];
                r.x += q4.x; r.y += q4.y; r.z += q4.z; r.w += q4.w;
            }
            if (RELU) {
                r.x = fmaxf(r.x, 0.f); r.y = fmaxf(r.y, 0.f);
                r.z = fmaxf(r.z, 0.f); r.w = fmaxf(r.w, 0.f);
            }
            if (OMODE == 0) {
                *(float4*)&C[(size_t)mi * N + nj] = r;
            } else {
                size_t o = ((size_t)(mi >> 10) * NHEAD + (nj >> 6)) * ((size_t)SEQ * DRED)
                         + (size_t)(mi & 1023) * DRED + (nj & 63);
                *(float4*)&C[o] = r;
            }
        }
    }
}

// ---------------------------------------------------------------------------
// Fused attention (flash-style, exact softmax, no mask).
// Q,K,V: [B,H,S,R] fp32.  Out: [B*S, H*R] (tok-major, head-concat columns).
// Grid: (S/64, B*H), 256 threads. smem = 3 * 16KB = 48KB.
// ---------------------------------------------------------------------------
__global__ __launch_bounds__(256)
void attn_kernel(const float* __restrict__ Q, const float* __restrict__ Kg,
                 const float* __restrict__ Vg, float* __restrict__ Out)
{
    __shared__ float QsT[64 * 64];   // [r][i]
    __shared__ float KsT[64 * 64];   // [r][j]; reused as P[i][j]
    __shared__ float Vs [64 * 64];   // [j][n]

    const int bh = blockIdx.y;
    const int b  = bh >> 4;
    const int h  = bh & 15;
    const int q0 = blockIdx.x * 64;

    const size_t base = (size_t)bh * SEQ * DRED;
    const float* Qb = Q  + base;
    const float* Kb = Kg + base;
    const float* Vb = Vg + base;

    const int t  = threadIdx.x;
    const int tx = t & 15;
    const int ty = t >> 4;

    // Load Q tile transposed
    #pragma unroll
    for (int rr = 0; rr < 4; rr++) {
        int idx = t + rr * 256;
        int i   = idx >> 4;
        int rc  = (idx & 15) * 4;
        float4 v = *(const float4*)&Qb[(size_t)(q0 + i) * DRED + rc];
        QsT[(rc + 0) * 64 + i] = v.x;
        QsT[(rc + 1) * 64 + i] = v.y;
        QsT[(rc + 2) * 64 + i] = v.z;
        QsT[(rc + 3) * 64 + i] = v.w;
    }

    float acc[4][4];
    float m_i[4], l_i[4];
    #pragma unroll
    for (int ii = 0; ii < 4; ii++) {
        m_i[ii] = -1e30f; l_i[ii] = 0.f;
        #pragma unroll
        for (int jj = 0; jj < 4; jj++) acc[ii][jj] = 0.f;
    }
    __syncthreads();

    for (int t0 = 0; t0 < SEQ; t0 += 64) {
        // Load K (transposed) and V (natural)
        #pragma unroll
        for (int rr = 0; rr < 4; rr++) {
            int idx = t + rr * 256;
            int j   = idx >> 4;
            int rc  = (idx & 15) * 4;
            float4 kv = *(const float4*)&Kb[(size_t)(t0 + j) * DRED + rc];
            KsT[(rc + 0) * 64 + j] = kv.x;
            KsT[(rc + 1) * 64 + j] = kv.y;
            KsT[(rc + 2) * 64 + j] = kv.z;
            KsT[(rc + 3) * 64 + j] = kv.w;
            float4 vv = *(const float4*)&Vb[(size_t)(t0 + j) * DRED + rc];
            *(float4*)&Vs[j * 64 + rc] = vv;
        }
        __syncthreads();

        // S = Q K^T  (micro 4x4)
        float s[4][4];
        #pragma unroll
        for (int ii = 0; ii < 4; ii++)
            #pragma unroll
            for (int jj = 0; jj < 4; jj++) s[ii][jj] = 0.f;

        #pragma unroll 8
        for (int r = 0; r < 64; r++) {
            float4 qa = *(const float4*)&QsT[r * 64 + ty * 4];
            float4 kb = *(const float4*)&KsT[r * 64 + tx * 4];
            float qa4[4] = {qa.x, qa.y, qa.z, qa.w};
            float kb4[4] = {kb.x, kb.y, kb.z, kb.w};
            #pragma unroll
            for (int ii = 0; ii < 4; ii++)
                #pragma unroll
                for (int jj = 0; jj < 4; jj++)
                    s[ii][jj] += qa4[ii] * kb4[jj];
        }

        // Online softmax update (scale 1/sqrt(64) = 0.125)
        #pragma unroll
        for (int ii = 0; ii < 4; ii++) {
            #pragma unroll
            for (int jj = 0; jj < 4; jj++) s[ii][jj] *= 0.125f;
            float mt = fmaxf(fmaxf(s[ii][0], s[ii][1]), fmaxf(s[ii][2], s[ii][3]));
            #pragma unroll
            for (int off = 8; off >= 1; off >>= 1)
                mt = fmaxf(mt, __shfl_xor_sync(0xffffffffu, mt, off));
            float mn = fmaxf(m_i[ii], mt);
            float alpha = __expf(m_i[ii] - mn);
            m_i[ii] = mn;
            float rs = 0.f;
            #pragma unroll
            for (int jj = 0; jj < 4; jj++) {
                float p = __expf(s[ii][jj] - mn);
                s[ii][jj] = p;
                rs += p;
            }
            #pragma unroll
            for (int off = 8; off >= 1; off >>= 1)
                rs += __shfl_xor_sync(0xffffffffu, rs, off);
            l_i[ii] = l_i[ii] * alpha + rs;
            #pragma unroll
            for (int jj = 0; jj < 4; jj++) acc[ii][jj] *= alpha;
        }

        __syncthreads();   // all threads done reading KsT
        // Store P into KsT as P[i][j]
        #pragma unroll
        for (int ii = 0; ii < 4; ii++) {
            float4 pv;
            pv.x = s[ii][0]; pv.y = s[ii][1]; pv.z = s[ii][2]; pv.w = s[ii][3];
            *(float4*)&KsT[(ty * 4 + ii) * 64 + tx * 4] = pv;
        }
        __syncthreads();

        // O += P V
        #pragma unroll 8
        for (int j = 0; j < 64; j++) {
            float4 vb = *(const float4*)&Vs[j * 64 + tx * 4];
            float vb4[4] = {vb.x, vb.y, vb.z, vb.w};
            float pa[4];
            #pragma unroll
            for (int ii = 0; ii < 4; ii++) pa[ii] = KsT[(ty * 4 + ii) * 64 + j];
            #pragma unroll
            for (int ii = 0; ii < 4; ii++)
                #pragma unroll
                for (int jj = 0; jj < 4; jj++)
                    acc[ii][jj] += pa[ii] * vb4[jj];
        }
        __syncthreads();   // safe to overwrite KsT/Vs next iter
    }

    // Write out: Out[(b*S + q0+i) * 1024 + h*64 + n]
    #pragma unroll
    for (int ii = 0; ii < 4; ii++) {
        float inv = 1.f / l_i[ii];
        float4 o;
        o.x = acc[ii][0] * inv; o.y = acc[ii][1] * inv;
        o.z = acc[ii][2] * inv; o.w = acc[ii][3] * inv;
        size_t off = ((size_t)b * SEQ + q0 + ty * 4 + ii) * DEMB + h * DRED + tx * 4;
        *(float4*)&Out[off] = o;
    }
}

// ---------------------------------------------------------------------------
// LayerNorm over rows of 1024, eps = 1e-3 (keras default, matches reference)
// ---------------------------------------------------------------------------
__global__ __launch_bounds__(256)
void ln_kernel(const float* __restrict__ in, const float* __restrict__ gam,
               const float* __restrict__ bet, float* __restrict__ out)
{
    __shared__ float red[16];
    const int row = blockIdx.x;
    const int t   = threadIdx.x;
    const float* p = in + (size_t)row * DEMB;

    float4 v = *(const float4*)&p[t * 4];
    float s  = v.x + v.y + v.z + v.w;
    float ss = v.x * v.x + v.y * v.y + v.z * v.z + v.w * v.w;
    #pragma unroll
    for (int o = 16; o >= 1; o >>= 1) {
        s  += __shfl_xor_sync(0xffffffffu, s, o);
        ss += __shfl_xor_sync(0xffffffffu, ss, o);
    }
    if ((t & 31) == 0) { red[t >> 5] = s; red[8 + (t >> 5)] = ss; }
    __syncthreads();
    s = 0.f; ss = 0.f;
    #pragma unroll
    for (int i = 0; i < 8; i++) { s += red[i]; ss += red[8 + i]; }

    float mean = s * (1.f / DEMB);
    float var  = ss * (1.f / DEMB) - mean * mean;
    float r    = rsqrtf(var + 1e-3f);

    float4 g4 = *(const float4*)&gam[t * 4];
    float4 b4 = *(const float4*)&bet[t * 4];
    float4 o;
    o.x = (v.x - mean) * r * g4.x + b4.x;
    o.y = (v.y - mean) * r * g4.y + b4.y;
    o.z = (v.z - mean) * r * g4.z + b4.z;
    o.w = (v.w - mean) * r * g4.w + b4.w;
    *(float4*)&out[(size_t)row * DEMB + t * 4] = o;
}

// ---------------------------------------------------------------------------
// Launch
// ---------------------------------------------------------------------------
extern "C" void kernel_launch(void* const* d_in, const int* in_sizes, int n_in,
                              void* d_out, int out_size)
{
    const float* x      = (const float*)d_in[0];
    const float* ctx    = (const float*)d_in[1];
    const float* sa_wq  = (const float*)d_in[2];
    const float* sa_bq  = (const float*)d_in[3];
    const float* sa_wk  = (const float*)d_in[4];
    const float* sa_bk  = (const float*)d_in[5];
    const float* sa_wv  = (const float*)d_in[6];
    const float* sa_bv  = (const float*)d_in[7];
    const float* sa_wo  = (const float*)d_in[8];
    const float* sa_bo  = (const float*)d_in[9];
    const float* ca_wq  = (const float*)d_in[10];
    const float* ca_bq  = (const float*)d_in[11];
    const float* ca_wk  = (const float*)d_in[12];
    const float* ca_bk  = (const float*)d_in[13];
    const float* ca_wv  = (const float*)d_in[14];
    const float* ca_bv  = (const float*)d_in[15];
    const float* ca_wo  = (const float*)d_in[16];
    const float* ca_bo  = (const float*)d_in[17];
    const float* ln1_g  = (const float*)d_in[18];
    const float* ln1_b  = (const float*)d_in[19];
    const float* ln2_g  = (const float*)d_in[20];
    const float* ln2_b  = (const float*)d_in[21];
    const float* ln3_g  = (const float*)d_in[22];
    const float* ln3_b  = (const float*)d_in[23];
    const float* ffn_w1 = (const float*)d_in[24];
    const float* ffn_b1 = (const float*)d_in[25];
    const float* ffn_w2 = (const float*)d_in[26];
    const float* ffn_b2 = (const float*)d_in[27];
    float* out = (float*)d_out;

    float *q, *k, *v, *att, *res, *ln1, *ln2, *ffn;
    cudaGetSymbolAddress((void**)&q,   g_q);
    cudaGetSymbolAddress((void**)&k,   g_k);
    cudaGetSymbolAddress((void**)&v,   g_v);
    cudaGetSymbolAddress((void**)&att, g_att);
    cudaGetSymbolAddress((void**)&res, g_res);
    cudaGetSymbolAddress((void**)&ln1, g_ln1);
    cudaGetSymbolAddress((void**)&ln2, g_ln2);
    cudaGetSymbolAddress((void**)&ffn, g_ffn);

    dim3 gProj(DEMB / 128, NTOK / 128);    // (8, 32)
    dim3 gFfn1(DFFN / 128, NTOK / 128);    // (32, 32)
    dim3 gAttn(SEQ / 64, BQ * NHEAD);      // (16, 64)

    // ---- self attention ----
    sgemm<1, 1, true, false, false><<<gProj, 256>>>(x, sa_wq, sa_bq, nullptr, q, NTOK, DEMB, DEMB);
    sgemm<1, 1, true, false, false><<<gProj, 256>>>(x, sa_wk, sa_bk, nullptr, k, NTOK, DEMB, DEMB);
    sgemm<1, 1, true, false, false><<<gProj, 256>>>(x, sa_wv, sa_bv, nullptr, v, NTOK, DEMB, DEMB);
    attn_kernel<<<gAttn, 256>>>(q, k, v, att);
    sgemm<0, 0, true, true, false><<<gProj, 256>>>(att, sa_wo, sa_bo, x, res, NTOK, DEMB, DEMB);
    ln_kernel<<<NTOK, 256>>>(res, ln1_g, ln1_b, ln1);

    // ---- cross attention ----
    sgemm<1, 1, true, false, false><<<gProj, 256>>>(ln1, ca_wq, ca_bq, nullptr, q, NTOK, DEMB, DEMB);
    sgemm<1, 1, true, false, false><<<gProj, 256>>>(ctx, ca_wk, ca_bk, nullptr, k, NTOK, DEMB, DEMB);
    sgemm<1, 1, true, false, false><<<gProj, 256>>>(ctx, ca_wv, ca_bv, nullptr, v, NTOK, DEMB, DEMB);
    attn_kernel<<<gAttn, 256>>>(q, k, v, att);
    sgemm<0, 0, true, true, false><<<gProj, 256>>>(att, ca_wo, ca_bo, ln1, res, NTOK, DEMB, DEMB);
    ln_kernel<<<NTOK, 256>>>(res, ln2_g, ln2_b, ln2);

    // ---- FFN ----
    sgemm<0, 0, true, false, true><<<gFfn1, 256>>>(ln2, ffn_w1, ffn_b1, nullptr, ffn, NTOK, DFFN, DEMB);
    sgemm<0, 0, true, true, false><<<gProj, 256>>>(ffn, ffn_w2, ffn_b2, ln2, res, NTOK, DEMB, DFFN);
    ln_kernel<<<NTOK, 256>>>(res, ln3_g, ln3_b, out);
}

// round 5
// speedup vs baseline: 1.6028x; 1.6028x over previous
#include <cuda_runtime.h>
#include <cuda_bf16.h>
#include <cstdint>
#include <cstddef>

// Problem constants
#define BQ 4
#define SEQ 1024
#define DEMB 1024
#define NHEAD 16
#define DRED 64
#define NTOK (BQ*SEQ)          // 4096
#define DFFN (4*DEMB)          // 4096

// ---------------------------------------------------------------------------
// Scratch (static device memory; no allocations anywhere)
// ---------------------------------------------------------------------------
__device__ float g_q  [(size_t)BQ*NHEAD*SEQ*DRED];
__device__ float g_k  [(size_t)BQ*NHEAD*SEQ*DRED];
__device__ float g_v  [(size_t)BQ*NHEAD*SEQ*DRED];
__device__ float g_att[(size_t)NTOK*DEMB];
__device__ float g_res[(size_t)NTOK*DEMB];
__device__ float g_ln1[(size_t)NTOK*DEMB];
__device__ float g_ln2[(size_t)NTOK*DEMB];
__device__ float g_ffn[(size_t)NTOK*DFFN];

// bf16 weight scratch: transposed [N,K] hi/lo.
//  offsets (units of 1M elements):
//  0:sa_wq 1:sa_wk 2:sa_wv 3:sa_wo 4:ca_wq 5:ca_wk 6:ca_wv 7:ca_wo
//  8..11: ffn_w1 (4M)   12..15: ffn_w2 (4M)
#define WME (1024*1024)
__device__ __nv_bfloat16 g_whi[(size_t)16*WME];
__device__ __nv_bfloat16 g_wlo[(size_t)16*WME];

// ---------------------------------------------------------------------------
// PTX helpers (all baseline-PTX features: sm_80/sm_90 non-arch-specific)
// ---------------------------------------------------------------------------
__device__ __forceinline__ uint32_t smem_to_u32(const void* p) {
    uint32_t a;
    asm("{ .reg .u64 t; cvta.to.shared.u64 t, %1; cvt.u32.u64 %0, t; }"
        : "=r"(a) : "l"(p));
    return a;
}
__device__ __forceinline__ void cp_async16(uint32_t s, const void* g) {
    asm volatile("cp.async.cg.shared.global [%0], [%1], 16;" :: "r"(s), "l"(g));
}
#define CP_COMMIT() asm volatile("cp.async.commit_group;" ::: "memory")
#define CP_WAIT0()  asm volatile("cp.async.wait_group 0;" ::: "memory")

__device__ __forceinline__ void ldm_x4(uint32_t* r, uint32_t addr) {
    asm volatile("ldmatrix.sync.aligned.m8n8.x4.shared.b16 {%0,%1,%2,%3}, [%4];"
        : "=r"(r[0]), "=r"(r[1]), "=r"(r[2]), "=r"(r[3]) : "r"(addr));
}
__device__ __forceinline__ void mma_bf16(float* c, const uint32_t* a,
                                         uint32_t b0, uint32_t b1) {
    asm volatile(
        "mma.sync.aligned.m16n8k16.row.col.f32.bf16.bf16.f32 "
        "{%0,%1,%2,%3}, {%4,%5,%6,%7}, {%8,%9}, {%0,%1,%2,%3};"
        : "+f"(c[0]), "+f"(c[1]), "+f"(c[2]), "+f"(c[3])
        : "r"(a[0]), "r"(a[1]), "r"(a[2]), "r"(a[3]), "r"(b0), "r"(b1));
}

// ---------------------------------------------------------------------------
// Weight transpose + hi/lo bf16 split.
// Input block z: in + z*R*C, [R,C] row-major fp32.
// Output row n = z*C + c (length R): out[n*R + r] = in[z][r][c].
// ---------------------------------------------------------------------------
__global__ __launch_bounds__(256)
void wconv(const float* __restrict__ in, __nv_bfloat16* __restrict__ ohi,
           __nv_bfloat16* __restrict__ olo, int R, int C)
{
    __shared__ float tile[32][33];
    const int bz = blockIdx.z;
    const float* ip = in + (size_t)bz * R * C;
    const int r0 = blockIdx.y * 32, c0 = blockIdx.x * 32;
    const int tx = threadIdx.x & 31;
    const int ty = threadIdx.x >> 5;   // 0..7

    #pragma unroll
    for (int i = 0; i < 32; i += 8)
        tile[ty + i][tx] = ip[(size_t)(r0 + ty + i) * C + c0 + tx];
    __syncthreads();

    #pragma unroll
    for (int i = 0; i < 32; i += 8) {
        float x = tile[tx][ty + i];
        __nv_bfloat16 h = __float2bfloat16_rn(x);
        __nv_bfloat16 l = __float2bfloat16_rn(x - __bfloat162float(h));
        size_t o = ((size_t)bz * C + c0 + ty + i) * R + r0 + tx;
        ohi[o] = h;
        olo[o] = l;
    }
}

// ---------------------------------------------------------------------------
// Tensor-core GEMM via mma.sync (bf16, 3-term hi/lo split, fp32 accum).
// C[M,N] = A[M,K](fp32) * W[N,K]^T  (+bias) (+resid) (relu?)
// CTA 128x128, BK=32, double-buffered smem, cp.async weights.
// smem row pitch 80B (64B data + 16B pad -> conflict-free ldmatrix).
//  OMODE 0: C row-major [M,N];  OMODE 1: C in [B,H,S,R] (m=b*S+s, n=h*64+r)
// ---------------------------------------------------------------------------
#define PITCH 80
#define OFF_ALO 10240
#define OFF_WHI 20480
#define OFF_WLO 30720
#define BUFSZ   40960
#define GSMEM   (2*BUFSZ)

template<int OMODE, bool RESID, bool RELU>
__global__ __launch_bounds__(256)
void tgemm(const float* __restrict__ A, const __nv_bfloat16* __restrict__ Whi,
           const __nv_bfloat16* __restrict__ Wlo, const float* __restrict__ bias,
           const float* __restrict__ resid, float* __restrict__ C,
           int M, int N, int K)
{
    extern __shared__ char smem[];
    const uint32_t sb = smem_to_u32(smem);

    const int t    = threadIdx.x;
    const int lane = t & 31;
    const int wid  = t >> 5;
    const int wm   = wid & 3;       // warp M index (0..3) -> 32 rows
    const int wn   = wid >> 2;      // warp N index (0..1) -> 64 cols
    const int m0   = blockIdx.y * 128;
    const int n0   = blockIdx.x * 128;
    const int nch  = K >> 5;

    // A stage roles: thread t -> row t>>1, k-half (t&1)*16
    const int arow  = t >> 1;
    const int akoff = (t & 1) * 16;
    const uint32_t aStOff = (uint32_t)arow * PITCH + (t & 1) * 32;

    // W cp.async roles: 2 chunk-ids per thread (hi & lo each)
    const int q0r = (2 * t) >> 2,     q0c = (2 * t) & 3;
    const int q1r = (2 * t + 1) >> 2, q1c = (2 * t + 1) & 3;

    float acc[2][8][4];
    #pragma unroll
    for (int a = 0; a < 2; a++)
        #pragma unroll
        for (int b = 0; b < 8; b++)
            #pragma unroll
            for (int d = 0; d < 4; d++) acc[a][b][d] = 0.f;

    auto loadW = [&](int k0, uint32_t bufo) {
        cp_async16(sb + bufo + OFF_WHI + q0r * PITCH + q0c * 16,
                   Whi + (size_t)(n0 + q0r) * K + k0 + q0c * 8);
        cp_async16(sb + bufo + OFF_WLO + q0r * PITCH + q0c * 16,
                   Wlo + (size_t)(n0 + q0r) * K + k0 + q0c * 8);
        cp_async16(sb + bufo + OFF_WHI + q1r * PITCH + q1c * 16,
                   Whi + (size_t)(n0 + q1r) * K + k0 + q1c * 8);
        cp_async16(sb + bufo + OFF_WLO + q1r * PITCH + q1c * 16,
                   Wlo + (size_t)(n0 + q1r) * K + k0 + q1c * 8);
        CP_COMMIT();
    };
    auto loadA = [&](int k0, float4* f4) {
        const float4* ap = (const float4*)(A + (size_t)(m0 + arow) * K + k0 + akoff);
        #pragma unroll
        for (int i = 0; i < 4; i++) f4[i] = ap[i];
    };
    auto storeA = [&](const float4* f4, uint32_t bufo) {
        float f[16];
        #pragma unroll
        for (int i = 0; i < 4; i++) {
            f[4*i+0] = f4[i].x; f[4*i+1] = f4[i].y;
            f[4*i+2] = f4[i].z; f[4*i+3] = f4[i].w;
        }
        uint32_t hp[8], lp[8];
        #pragma unroll
        for (int j = 0; j < 8; j++) {
            __nv_bfloat16 h0 = __float2bfloat16_rn(f[2*j]);
            __nv_bfloat16 h1 = __float2bfloat16_rn(f[2*j+1]);
            __nv_bfloat16 l0 = __float2bfloat16_rn(f[2*j]   - __bfloat162float(h0));
            __nv_bfloat16 l1 = __float2bfloat16_rn(f[2*j+1] - __bfloat162float(h1));
            __nv_bfloat162 hh = __halves2bfloat162(h0, h1);
            __nv_bfloat162 ll = __halves2bfloat162(l0, l1);
            hp[j] = *(uint32_t*)&hh;
            lp[j] = *(uint32_t*)&ll;
        }
        *(uint4*)(smem + bufo + aStOff)           = make_uint4(hp[0], hp[1], hp[2], hp[3]);
        *(uint4*)(smem + bufo + aStOff + 16)      = make_uint4(hp[4], hp[5], hp[6], hp[7]);
        *(uint4*)(smem + bufo + OFF_ALO + aStOff)      = make_uint4(lp[0], lp[1], lp[2], lp[3]);
        *(uint4*)(smem + bufo + OFF_ALO + aStOff + 16) = make_uint4(lp[4], lp[5], lp[6], lp[7]);
    };

    // per-thread ldmatrix base addresses
    const uint32_t aBase = sb + (uint32_t)(wm * 32 + (lane & 15)) * PITCH + (lane >> 4) * 16;
    const uint32_t wBase = sb + OFF_WHI
        + (uint32_t)(wn * 64 + ((lane >> 4) << 3) + (lane & 7)) * PITCH
        + ((lane >> 3) & 1) * 16;

    auto compute = [&](uint32_t bufo) {
        #pragma unroll
        for (int ks = 0; ks < 2; ks++) {
            uint32_t ahi[2][4], alo[2][4];
            #pragma unroll
            for (int mt = 0; mt < 2; mt++) {
                ldm_x4(ahi[mt], aBase + bufo + mt * (16*PITCH) + ks * 32);
                ldm_x4(alo[mt], aBase + bufo + OFF_ALO + mt * (16*PITCH) + ks * 32);
            }
            #pragma unroll
            for (int ng = 0; ng < 2; ng++) {
                uint32_t bh[8], bl[8];
                #pragma unroll
                for (int p = 0; p < 2; p++) {
                    ldm_x4(bh + p*4, wBase + bufo + (ng*2 + p) * (16*PITCH) + ks * 32);
                    ldm_x4(bl + p*4, wBase + bufo + (OFF_WLO - OFF_WHI)
                                   + (ng*2 + p) * (16*PITCH) + ks * 32);
                }
                #pragma unroll
                for (int nt = 0; nt < 4; nt++) {
                    #pragma unroll
                    for (int mt = 0; mt < 2; mt++) {
                        float* cc = acc[mt][ng*4 + nt];
                        mma_bf16(cc, ahi[mt], bh[nt*2], bh[nt*2+1]);
                        mma_bf16(cc, alo[mt], bh[nt*2], bh[nt*2+1]);
                        mma_bf16(cc, ahi[mt], bl[nt*2], bl[nt*2+1]);
                    }
                }
            }
        }
    };

    // ---- prologue: chunk 0 ----
    {
        loadW(0, 0);
        float4 f4[4];
        loadA(0, f4);
        storeA(f4, 0);
        CP_WAIT0();
        __syncthreads();
    }

    // ---- main loop ----
    for (int c = 0; c < nch; c++) {
        const uint32_t bufo  = (c & 1) * BUFSZ;
        const uint32_t nbufo = BUFSZ - bufo;
        const bool hasNext = (c + 1 < nch);
        float4 f4[4];
        if (hasNext) {
            loadW((c + 1) << 5, nbufo);
            loadA((c + 1) << 5, f4);
        }
        compute(bufo);
        if (hasNext) {
            storeA(f4, nbufo);
            CP_WAIT0();
        }
        __syncthreads();
    }

    // ---- epilogue ----
    #pragma unroll
    for (int mt = 0; mt < 2; mt++) {
        const int m = m0 + wm * 32 + mt * 16 + (lane >> 2);
        #pragma unroll
        for (int j = 0; j < 8; j++) {
            const int n = n0 + wn * 64 + j * 8 + (lane & 3) * 2;
            float2 v0 = make_float2(acc[mt][j][0], acc[mt][j][1]);
            float2 v1 = make_float2(acc[mt][j][2], acc[mt][j][3]);
            float2 b2 = *(const float2*)&bias[n];
            v0.x += b2.x; v0.y += b2.y;
            v1.x += b2.x; v1.y += b2.y;
            if (RESID) {
                float2 r0 = *(const float2*)&resid[(size_t)m * N + n];
                float2 r1 = *(const float2*)&resid[(size_t)(m + 8) * N + n];
                v0.x += r0.x; v0.y += r0.y;
                v1.x += r1.x; v1.y += r1.y;
            }
            if (RELU) {
                v0.x = fmaxf(v0.x, 0.f); v0.y = fmaxf(v0.y, 0.f);
                v1.x = fmaxf(v1.x, 0.f); v1.y = fmaxf(v1.y, 0.f);
            }
            if (OMODE == 0) {
                *(float2*)&C[(size_t)m * N + n]       = v0;
                *(float2*)&C[(size_t)(m + 8) * N + n] = v1;
            } else {
                size_t o0 = ((size_t)(m >> 10) * NHEAD + (n >> 6)) * ((size_t)SEQ * DRED)
                          + (size_t)(m & (SEQ - 1)) * DRED + (n & 63);
                size_t o1 = ((size_t)((m + 8) >> 10) * NHEAD + (n >> 6)) * ((size_t)SEQ * DRED)
                          + (size_t)((m + 8) & (SEQ - 1)) * DRED + (n & 63);
                *(float2*)&C[o0] = v0;
                *(float2*)&C[o1] = v1;
            }
        }
    }
}

// ---------------------------------------------------------------------------
// Fused attention (flash-style, exact softmax, no mask).
// Q,K,V: [B,H,S,R] fp32.  Out: [B*S, H*R].
// ---------------------------------------------------------------------------
__global__ __launch_bounds__(256)
void attn_kernel(const float* __restrict__ Q, const float* __restrict__ Kg,
                 const float* __restrict__ Vg, float* __restrict__ Out)
{
    __shared__ float QsT[64 * 64];
    __shared__ float KsT[64 * 64];
    __shared__ float Vs [64 * 64];

    const int bh = blockIdx.y;
    const int b  = bh >> 4;
    const int h  = bh & 15;
    const int q0 = blockIdx.x * 64;

    const size_t base = (size_t)bh * SEQ * DRED;
    const float* Qb = Q  + base;
    const float* Kb = Kg + base;
    const float* Vb = Vg + base;

    const int t  = threadIdx.x;
    const int tx = t & 15;
    const int ty = t >> 4;

    #pragma unroll
    for (int rr = 0; rr < 4; rr++) {
        int idx = t + rr * 256;
        int i   = idx >> 4;
        int rc  = (idx & 15) * 4;
        float4 v = *(const float4*)&Qb[(size_t)(q0 + i) * DRED + rc];
        QsT[(rc + 0) * 64 + i] = v.x;
        QsT[(rc + 1) * 64 + i] = v.y;
        QsT[(rc + 2) * 64 + i] = v.z;
        QsT[(rc + 3) * 64 + i] = v.w;
    }

    float acc[4][4];
    float m_i[4], l_i[4];
    #pragma unroll
    for (int ii = 0; ii < 4; ii++) {
        m_i[ii] = -1e30f; l_i[ii] = 0.f;
        #pragma unroll
        for (int jj = 0; jj < 4; jj++) acc[ii][jj] = 0.f;
    }
    __syncthreads();

    for (int t0 = 0; t0 < SEQ; t0 += 64) {
        #pragma unroll
        for (int rr = 0; rr < 4; rr++) {
            int idx = t + rr * 256;
            int j   = idx >> 4;
            int rc  = (idx & 15) * 4;
            float4 kv = *(const float4*)&Kb[(size_t)(t0 + j) * DRED + rc];
            KsT[(rc + 0) * 64 + j] = kv.x;
            KsT[(rc + 1) * 64 + j] = kv.y;
            KsT[(rc + 2) * 64 + j] = kv.z;
            KsT[(rc + 3) * 64 + j] = kv.w;
            float4 vv = *(const float4*)&Vb[(size_t)(t0 + j) * DRED + rc];
            *(float4*)&Vs[j * 64 + rc] = vv;
        }
        __syncthreads();

        float s[4][4];
        #pragma unroll
        for (int ii = 0; ii < 4; ii++)
            #pragma unroll
            for (int jj = 0; jj < 4; jj++) s[ii][jj] = 0.f;

        #pragma unroll 8
        for (int r = 0; r < 64; r++) {
            float4 qa = *(const float4*)&QsT[r * 64 + ty * 4];
            float4 kb = *(const float4*)&KsT[r * 64 + tx * 4];
            float qa4[4] = {qa.x, qa.y, qa.z, qa.w};
            float kb4[4] = {kb.x, kb.y, kb.z, kb.w};
            #pragma unroll
            for (int ii = 0; ii < 4; ii++)
                #pragma unroll
                for (int jj = 0; jj < 4; jj++)
                    s[ii][jj] += qa4[ii] * kb4[jj];
        }

        #pragma unroll
        for (int ii = 0; ii < 4; ii++) {
            #pragma unroll
            for (int jj = 0; jj < 4; jj++) s[ii][jj] *= 0.125f;
            float mt = fmaxf(fmaxf(s[ii][0], s[ii][1]), fmaxf(s[ii][2], s[ii][3]));
            #pragma unroll
            for (int off = 8; off >= 1; off >>= 1)
                mt = fmaxf(mt, __shfl_xor_sync(0xffffffffu, mt, off));
            float mn = fmaxf(m_i[ii], mt);
            float alpha = __expf(m_i[ii] - mn);
            m_i[ii] = mn;
            float rs = 0.f;
            #pragma unroll
            for (int jj = 0; jj < 4; jj++) {
                float p = __expf(s[ii][jj] - mn);
                s[ii][jj] = p;
                rs += p;
            }
            #pragma unroll
            for (int off = 8; off >= 1; off >>= 1)
                rs += __shfl_xor_sync(0xffffffffu, rs, off);
            l_i[ii] = l_i[ii] * alpha + rs;
            #pragma unroll
            for (int jj = 0; jj < 4; jj++) acc[ii][jj] *= alpha;
        }

        __syncthreads();
        #pragma unroll
        for (int ii = 0; ii < 4; ii++) {
            float4 pv;
            pv.x = s[ii][0]; pv.y = s[ii][1]; pv.z = s[ii][2]; pv.w = s[ii][3];
            *(float4*)&KsT[(ty * 4 + ii) * 64 + tx * 4] = pv;
        }
        __syncthreads();

        #pragma unroll 8
        for (int j = 0; j < 64; j++) {
            float4 vb = *(const float4*)&Vs[j * 64 + tx * 4];
            float vb4[4] = {vb.x, vb.y, vb.z, vb.w};
            float pa[4];
            #pragma unroll
            for (int ii = 0; ii < 4; ii++) pa[ii] = KsT[(ty * 4 + ii) * 64 + j];
            #pragma unroll
            for (int ii = 0; ii < 4; ii++)
                #pragma unroll
                for (int jj = 0; jj < 4; jj++)
                    acc[ii][jj] += pa[ii] * vb4[jj];
        }
        __syncthreads();
    }

    #pragma unroll
    for (int ii = 0; ii < 4; ii++) {
        float inv = 1.f / l_i[ii];
        float4 o;
        o.x = acc[ii][0] * inv; o.y = acc[ii][1] * inv;
        o.z = acc[ii][2] * inv; o.w = acc[ii][3] * inv;
        size_t off = ((size_t)b * SEQ + q0 + ty * 4 + ii) * DEMB + h * DRED + tx * 4;
        *(float4*)&Out[off] = o;
    }
}

// ---------------------------------------------------------------------------
// LayerNorm over rows of 1024, eps = 1e-3
// ---------------------------------------------------------------------------
__global__ __launch_bounds__(256)
void ln_kernel(const float* __restrict__ in, const float* __restrict__ gam,
               const float* __restrict__ bet, float* __restrict__ out)
{
    __shared__ float red[16];
    const int row = blockIdx.x;
    const int t   = threadIdx.x;
    const float* p = in + (size_t)row * DEMB;

    float4 v = *(const float4*)&p[t * 4];
    float s  = v.x + v.y + v.z + v.w;
    float ss = v.x * v.x + v.y * v.y + v.z * v.z + v.w * v.w;
    #pragma unroll
    for (int o = 16; o >= 1; o >>= 1) {
        s  += __shfl_xor_sync(0xffffffffu, s, o);
        ss += __shfl_xor_sync(0xffffffffu, ss, o);
    }
    if ((t & 31) == 0) { red[t >> 5] = s; red[8 + (t >> 5)] = ss; }
    __syncthreads();
    s = 0.f; ss = 0.f;
    #pragma unroll
    for (int i = 0; i < 8; i++) { s += red[i]; ss += red[8 + i]; }

    float mean = s * (1.f / DEMB);
    float var  = ss * (1.f / DEMB) - mean * mean;
    float r    = rsqrtf(var + 1e-3f);

    float4 g4 = *(const float4*)&gam[t * 4];
    float4 b4 = *(const float4*)&bet[t * 4];
    float4 o;
    o.x = (v.x - mean) * r * g4.x + b4.x;
    o.y = (v.y - mean) * r * g4.y + b4.y;
    o.z = (v.z - mean) * r * g4.z + b4.z;
    o.w = (v.w - mean) * r * g4.w + b4.w;
    *(float4*)&out[(size_t)row * DEMB + t * 4] = o;
}

// ---------------------------------------------------------------------------
// Launch
// ---------------------------------------------------------------------------
extern "C" void kernel_launch(void* const* d_in, const int* in_sizes, int n_in,
                              void* d_out, int out_size)
{
    const float* x      = (const float*)d_in[0];
    const float* ctx    = (const float*)d_in[1];
    const float* sa_wq  = (const float*)d_in[2];
    const float* sa_bq  = (const float*)d_in[3];
    const float* sa_wk  = (const float*)d_in[4];
    const float* sa_bk  = (const float*)d_in[5];
    const float* sa_wv  = (const float*)d_in[6];
    const float* sa_bv  = (const float*)d_in[7];
    const float* sa_wo  = (const float*)d_in[8];
    const float* sa_bo  = (const float*)d_in[9];
    const float* ca_wq  = (const float*)d_in[10];
    const float* ca_bq  = (const float*)d_in[11];
    const float* ca_wk  = (const float*)d_in[12];
    const float* ca_bk  = (const float*)d_in[13];
    const float* ca_wv  = (const float*)d_in[14];
    const float* ca_bv  = (const float*)d_in[15];
    const float* ca_wo  = (const float*)d_in[16];
    const float* ca_bo  = (const float*)d_in[17];
    const float* ln1_g  = (const float*)d_in[18];
    const float* ln1_b  = (const float*)d_in[19];
    const float* ln2_g  = (const float*)d_in[20];
    const float* ln2_b  = (const float*)d_in[21];
    const float* ln3_g  = (const float*)d_in[22];
    const float* ln3_b  = (const float*)d_in[23];
    const float* ffn_w1 = (const float*)d_in[24];
    const float* ffn_b1 = (const float*)d_in[25];
    const float* ffn_w2 = (const float*)d_in[26];
    const float* ffn_b2 = (const float*)d_in[27];
    float* out = (float*)d_out;

    float *q, *k, *v, *att, *res, *ln1, *ln2, *ffn;
    __nv_bfloat16 *whi, *wlo;
    cudaGetSymbolAddress((void**)&q,   g_q);
    cudaGetSymbolAddress((void**)&k,   g_k);
    cudaGetSymbolAddress((void**)&v,   g_v);
    cudaGetSymbolAddress((void**)&att, g_att);
    cudaGetSymbolAddress((void**)&res, g_res);
    cudaGetSymbolAddress((void**)&ln1, g_ln1);
    cudaGetSymbolAddress((void**)&ln2, g_ln2);
    cudaGetSymbolAddress((void**)&ffn, g_ffn);
    cudaGetSymbolAddress((void**)&whi, g_whi);
    cudaGetSymbolAddress((void**)&wlo, g_wlo);

    cudaFuncSetAttribute(tgemm<1, false, false>, cudaFuncAttributeMaxDynamicSharedMemorySize, GSMEM);
    cudaFuncSetAttribute(tgemm<0, true,  false>, cudaFuncAttributeMaxDynamicSharedMemorySize, GSMEM);
    cudaFuncSetAttribute(tgemm<0, false, true >, cudaFuncAttributeMaxDynamicSharedMemorySize, GSMEM);

    // ---- weight conversion: transpose + hi/lo bf16 split ----
    dim3 tpP(2, 32, 16);
    wconv<<<tpP, 256>>>(sa_wq, whi + (size_t)0*WME, wlo + (size_t)0*WME, 1024, 64);
    wconv<<<tpP, 256>>>(sa_wk, whi + (size_t)1*WME, wlo + (size_t)1*WME, 1024, 64);
    wconv<<<tpP, 256>>>(sa_wv, whi + (size_t)2*WME, wlo + (size_t)2*WME, 1024, 64);
    dim3 tpO(32, 32, 1);
    wconv<<<tpO, 256>>>(sa_wo, whi + (size_t)3*WME, wlo + (size_t)3*WME, 1024, 1024);
    wconv<<<tpP, 256>>>(ca_wq, whi + (size_t)4*WME, wlo + (size_t)4*WME, 1024, 64);
    wconv<<<tpP, 256>>>(ca_wk, whi + (size_t)5*WME, wlo + (size_t)5*WME, 1024, 64);
    wconv<<<tpP, 256>>>(ca_wv, whi + (size_t)6*WME, wlo + (size_t)6*WME, 1024, 64);
    wconv<<<tpO, 256>>>(ca_wo, whi + (size_t)7*WME, wlo + (size_t)7*WME, 1024, 1024);
    dim3 tpF1(128, 32, 1);
    wconv<<<tpF1, 256>>>(ffn_w1, whi + (size_t)8*WME,  wlo + (size_t)8*WME,  1024, 4096);
    dim3 tpF2(32, 128, 1);
    wconv<<<tpF2, 256>>>(ffn_w2, whi + (size_t)12*WME, wlo + (size_t)12*WME, 4096, 1024);

    dim3 gProj(DEMB / 128, NTOK / 128);    // (8, 32)
    dim3 gFfn1(DFFN / 128, NTOK / 128);    // (32, 32)
    dim3 gAttn(SEQ / 64, BQ * NHEAD);      // (16, 64)

    // ---- self attention ----
    tgemm<1, false, false><<<gProj, 256, GSMEM>>>(x, whi + 0*WME, wlo + 0*WME, sa_bq, nullptr, q, NTOK, DEMB, DEMB);
    tgemm<1, false, false><<<gProj, 256, GSMEM>>>(x, whi + 1*WME, wlo + 1*WME, sa_bk, nullptr, k, NTOK, DEMB, DEMB);
    tgemm<1, false, false><<<gProj, 256, GSMEM>>>(x, whi + 2*WME, wlo + 2*WME, sa_bv, nullptr, v, NTOK, DEMB, DEMB);
    attn_kernel<<<gAttn, 256>>>(q, k, v, att);
    tgemm<0, true, false><<<gProj, 256, GSMEM>>>(att, whi + 3*WME, wlo + 3*WME, sa_bo, x, res, NTOK, DEMB, DEMB);
    ln_kernel<<<NTOK, 256>>>(res, ln1_g, ln1_b, ln1);

    // ---- cross attention ----
    tgemm<1, false, false><<<gProj, 256, GSMEM>>>(ln1, whi + 4*WME, wlo + 4*WME, ca_bq, nullptr, q, NTOK, DEMB, DEMB);
    tgemm<1, false, false><<<gProj, 256, GSMEM>>>(ctx, whi + 5*WME, wlo + 5*WME, ca_bk, nullptr, k, NTOK, DEMB, DEMB);
    tgemm<1, false, false><<<gProj, 256, GSMEM>>>(ctx, whi + 6*WME, wlo + 6*WME, ca_bv, nullptr, v, NTOK, DEMB, DEMB);
    attn_kernel<<<gAttn, 256>>>(q, k, v, att);
    tgemm<0, true, false><<<gProj, 256, GSMEM>>>(att, whi + 7*WME, wlo + 7*WME, ca_bo, ln1, res, NTOK, DEMB, DEMB);
    ln_kernel<<<NTOK, 256>>>(res, ln2_g, ln2_b, ln2);

    // ---- FFN ----
    tgemm<0, false, true><<<gFfn1, 256, GSMEM>>>(ln2, whi + (size_t)8*WME, wlo + (size_t)8*WME, ffn_b1, nullptr, ffn, NTOK, DFFN, DEMB);
    tgemm<0, true, false><<<gProj, 256, GSMEM>>>(ffn, whi + (size_t)12*WME, wlo + (size_t)12*WME, ffn_b2, ln2, res, NTOK, DEMB, DFFN);
    ln_kernel<<<NTOK, 256>>>(res, ln3_g, ln3_b, out);
}

// round 6
// speedup vs baseline: 2.0698x; 1.2914x over previous
#include <cuda_runtime.h>
#include <cuda_bf16.h>
#include <cstdint>
#include <cstddef>

// Problem constants
#define BQ 4
#define SEQ 1024
#define DEMB 1024
#define NHEAD 16
#define DRED 64
#define NTOK (BQ*SEQ)          // 4096
#define DFFN (4*DEMB)          // 4096

// ---------------------------------------------------------------------------
// Scratch (static device memory; no allocations anywhere)
// ---------------------------------------------------------------------------
__device__ float g_q  [(size_t)BQ*NHEAD*SEQ*DRED];
__device__ float g_k  [(size_t)BQ*NHEAD*SEQ*DRED];
__device__ float g_v  [(size_t)BQ*NHEAD*SEQ*DRED];
__device__ float g_att[(size_t)NTOK*DEMB];
__device__ float g_res[(size_t)NTOK*DEMB];
__device__ float g_ln1[(size_t)NTOK*DEMB];
__device__ float g_ln2[(size_t)NTOK*DEMB];
__device__ float g_ffn[(size_t)NTOK*DFFN];

#define WME (1024*1024)
__device__ __nv_bfloat16 g_whi[(size_t)16*WME];
__device__ __nv_bfloat16 g_wlo[(size_t)16*WME];

// ---------------------------------------------------------------------------
// PTX helpers (baseline PTX only — no sm_103a-specific instructions)
// ---------------------------------------------------------------------------
__device__ __forceinline__ uint32_t smem_to_u32(const void* p) {
    uint32_t a;
    asm("{ .reg .u64 t; cvta.to.shared.u64 t, %1; cvt.u32.u64 %0, t; }"
        : "=r"(a) : "l"(p));
    return a;
}
__device__ __forceinline__ void cp_async16(uint32_t s, const void* g) {
    asm volatile("cp.async.cg.shared.global [%0], [%1], 16;" :: "r"(s), "l"(g));
}
#define CP_COMMIT() asm volatile("cp.async.commit_group;" ::: "memory")
#define CP_WAIT0()  asm volatile("cp.async.wait_group 0;" ::: "memory")

__device__ __forceinline__ void ldm_x4(uint32_t* r, uint32_t addr) {
    asm volatile("ldmatrix.sync.aligned.m8n8.x4.shared.b16 {%0,%1,%2,%3}, [%4];"
        : "=r"(r[0]), "=r"(r[1]), "=r"(r[2]), "=r"(r[3]) : "r"(addr));
}
__device__ __forceinline__ void ldm_x4_t(uint32_t* r, uint32_t addr) {
    asm volatile("ldmatrix.sync.aligned.m8n8.x4.trans.shared.b16 {%0,%1,%2,%3}, [%4];"
        : "=r"(r[0]), "=r"(r[1]), "=r"(r[2]), "=r"(r[3]) : "r"(addr));
}
__device__ __forceinline__ void mma_bf16(float* c, const uint32_t* a,
                                         uint32_t b0, uint32_t b1) {
    asm volatile(
        "mma.sync.aligned.m16n8k16.row.col.f32.bf16.bf16.f32 "
        "{%0,%1,%2,%3}, {%4,%5,%6,%7}, {%8,%9}, {%0,%1,%2,%3};"
        : "+f"(c[0]), "+f"(c[1]), "+f"(c[2]), "+f"(c[3])
        : "r"(a[0]), "r"(a[1]), "r"(a[2]), "r"(a[3]), "r"(b0), "r"(b1));
}
// split pair of fp32 into packed bf16x2 hi and lo parts
__device__ __forceinline__ void split2(float x, float y, uint32_t& hi, uint32_t& lo) {
    __nv_bfloat16 hx = __float2bfloat16_rn(x);
    __nv_bfloat16 hy = __float2bfloat16_rn(y);
    __nv_bfloat16 lx = __float2bfloat16_rn(x - __bfloat162float(hx));
    __nv_bfloat16 ly = __float2bfloat16_rn(y - __bfloat162float(hy));
    __nv_bfloat162 h2 = __halves2bfloat162(hx, hy);
    __nv_bfloat162 l2 = __halves2bfloat162(lx, ly);
    hi = *(uint32_t*)&h2;
    lo = *(uint32_t*)&l2;
}

// ---------------------------------------------------------------------------
// Weight transpose + hi/lo bf16 split (unchanged)
// ---------------------------------------------------------------------------
__global__ __launch_bounds__(256)
void wconv(const float* __restrict__ in, __nv_bfloat16* __restrict__ ohi,
           __nv_bfloat16* __restrict__ olo, int R, int C)
{
    __shared__ float tile[32][33];
    const int bz = blockIdx.z;
    const float* ip = in + (size_t)bz * R * C;
    const int r0 = blockIdx.y * 32, c0 = blockIdx.x * 32;
    const int tx = threadIdx.x & 31;
    const int ty = threadIdx.x >> 5;

    #pragma unroll
    for (int i = 0; i < 32; i += 8)
        tile[ty + i][tx] = ip[(size_t)(r0 + ty + i) * C + c0 + tx];
    __syncthreads();

    #pragma unroll
    for (int i = 0; i < 32; i += 8) {
        float x = tile[tx][ty + i];
        __nv_bfloat16 h = __float2bfloat16_rn(x);
        __nv_bfloat16 l = __float2bfloat16_rn(x - __bfloat162float(h));
        size_t o = ((size_t)bz * C + c0 + ty + i) * R + r0 + tx;
        ohi[o] = h;
        olo[o] = l;
    }
}

// ---------------------------------------------------------------------------
// Tensor-core GEMM via mma.sync (bf16 3-term hi/lo split) — unchanged from R5
// ---------------------------------------------------------------------------
#define PITCH 80
#define OFF_ALO 10240
#define OFF_WHI 20480
#define OFF_WLO 30720
#define BUFSZ   40960
#define GSMEM   (2*BUFSZ)

template<int OMODE, bool RESID, bool RELU>
__global__ __launch_bounds__(256)
void tgemm(const float* __restrict__ A, const __nv_bfloat16* __restrict__ Whi,
           const __nv_bfloat16* __restrict__ Wlo, const float* __restrict__ bias,
           const float* __restrict__ resid, float* __restrict__ C,
           int M, int N, int K)
{
    extern __shared__ char smem[];
    const uint32_t sb = smem_to_u32(smem);

    const int t    = threadIdx.x;
    const int lane = t & 31;
    const int wid  = t >> 5;
    const int wm   = wid & 3;
    const int wn   = wid >> 2;
    const int m0   = blockIdx.y * 128;
    const int n0   = blockIdx.x * 128;
    const int nch  = K >> 5;

    const int arow  = t >> 1;
    const int akoff = (t & 1) * 16;
    const uint32_t aStOff = (uint32_t)arow * PITCH + (t & 1) * 32;

    const int q0r = (2 * t) >> 2,     q0c = (2 * t) & 3;
    const int q1r = (2 * t + 1) >> 2, q1c = (2 * t + 1) & 3;

    float acc[2][8][4];
    #pragma unroll
    for (int a = 0; a < 2; a++)
        #pragma unroll
        for (int b = 0; b < 8; b++)
            #pragma unroll
            for (int d = 0; d < 4; d++) acc[a][b][d] = 0.f;

    auto loadW = [&](int k0, uint32_t bufo) {
        cp_async16(sb + bufo + OFF_WHI + q0r * PITCH + q0c * 16,
                   Whi + (size_t)(n0 + q0r) * K + k0 + q0c * 8);
        cp_async16(sb + bufo + OFF_WLO + q0r * PITCH + q0c * 16,
                   Wlo + (size_t)(n0 + q0r) * K + k0 + q0c * 8);
        cp_async16(sb + bufo + OFF_WHI + q1r * PITCH + q1c * 16,
                   Whi + (size_t)(n0 + q1r) * K + k0 + q1c * 8);
        cp_async16(sb + bufo + OFF_WLO + q1r * PITCH + q1c * 16,
                   Wlo + (size_t)(n0 + q1r) * K + k0 + q1c * 8);
        CP_COMMIT();
    };
    auto loadA = [&](int k0, float4* f4) {
        const float4* ap = (const float4*)(A + (size_t)(m0 + arow) * K + k0 + akoff);
        #pragma unroll
        for (int i = 0; i < 4; i++) f4[i] = ap[i];
    };
    auto storeA = [&](const float4* f4, uint32_t bufo) {
        float f[16];
        #pragma unroll
        for (int i = 0; i < 4; i++) {
            f[4*i+0] = f4[i].x; f[4*i+1] = f4[i].y;
            f[4*i+2] = f4[i].z; f[4*i+3] = f4[i].w;
        }
        uint32_t hp[8], lp[8];
        #pragma unroll
        for (int j = 0; j < 8; j++) split2(f[2*j], f[2*j+1], hp[j], lp[j]);
        *(uint4*)(smem + bufo + aStOff)           = make_uint4(hp[0], hp[1], hp[2], hp[3]);
        *(uint4*)(smem + bufo + aStOff + 16)      = make_uint4(hp[4], hp[5], hp[6], hp[7]);
        *(uint4*)(smem + bufo + OFF_ALO + aStOff)      = make_uint4(lp[0], lp[1], lp[2], lp[3]);
        *(uint4*)(smem + bufo + OFF_ALO + aStOff + 16) = make_uint4(lp[4], lp[5], lp[6], lp[7]);
    };

    const uint32_t aBase = sb + (uint32_t)(wm * 32 + (lane & 15)) * PITCH + (lane >> 4) * 16;
    const uint32_t wBase = sb + OFF_WHI
        + (uint32_t)(wn * 64 + ((lane >> 4) << 3) + (lane & 7)) * PITCH
        + ((lane >> 3) & 1) * 16;

    auto compute = [&](uint32_t bufo) {
        #pragma unroll
        for (int ks = 0; ks < 2; ks++) {
            uint32_t ahi[2][4], alo[2][4];
            #pragma unroll
            for (int mt = 0; mt < 2; mt++) {
                ldm_x4(ahi[mt], aBase + bufo + mt * (16*PITCH) + ks * 32);
                ldm_x4(alo[mt], aBase + bufo + OFF_ALO + mt * (16*PITCH) + ks * 32);
            }
            #pragma unroll
            for (int ng = 0; ng < 2; ng++) {
                uint32_t bh[8], bl[8];
                #pragma unroll
                for (int p = 0; p < 2; p++) {
                    ldm_x4(bh + p*4, wBase + bufo + (ng*2 + p) * (16*PITCH) + ks * 32);
                    ldm_x4(bl + p*4, wBase + bufo + (OFF_WLO - OFF_WHI)
                                   + (ng*2 + p) * (16*PITCH) + ks * 32);
                }
                #pragma unroll
                for (int nt = 0; nt < 4; nt++) {
                    #pragma unroll
                    for (int mt = 0; mt < 2; mt++) {
                        float* cc = acc[mt][ng*4 + nt];
                        mma_bf16(cc, ahi[mt], bh[nt*2], bh[nt*2+1]);
                        mma_bf16(cc, alo[mt], bh[nt*2], bh[nt*2+1]);
                        mma_bf16(cc, ahi[mt], bl[nt*2], bl[nt*2+1]);
                    }
                }
            }
        }
    };

    {
        loadW(0, 0);
        float4 f4[4];
        loadA(0, f4);
        storeA(f4, 0);
        CP_WAIT0();
        __syncthreads();
    }

    for (int c = 0; c < nch; c++) {
        const uint32_t bufo  = (c & 1) * BUFSZ;
        const uint32_t nbufo = BUFSZ - bufo;
        const bool hasNext = (c + 1 < nch);
        float4 f4[4];
        if (hasNext) {
            loadW((c + 1) << 5, nbufo);
            loadA((c + 1) << 5, f4);
        }
        compute(bufo);
        if (hasNext) {
            storeA(f4, nbufo);
            CP_WAIT0();
        }
        __syncthreads();
    }

    #pragma unroll
    for (int mt = 0; mt < 2; mt++) {
        const int m = m0 + wm * 32 + mt * 16 + (lane >> 2);
        #pragma unroll
        for (int j = 0; j < 8; j++) {
            const int n = n0 + wn * 64 + j * 8 + (lane & 3) * 2;
            float2 v0 = make_float2(acc[mt][j][0], acc[mt][j][1]);
            float2 v1 = make_float2(acc[mt][j][2], acc[mt][j][3]);
            float2 b2 = *(const float2*)&bias[n];
            v0.x += b2.x; v0.y += b2.y;
            v1.x += b2.x; v1.y += b2.y;
            if (RESID) {
                float2 r0 = *(const float2*)&resid[(size_t)m * N + n];
                float2 r1 = *(const float2*)&resid[(size_t)(m + 8) * N + n];
                v0.x += r0.x; v0.y += r0.y;
                v1.x += r1.x; v1.y += r1.y;
            }
            if (RELU) {
                v0.x = fmaxf(v0.x, 0.f); v0.y = fmaxf(v0.y, 0.f);
                v1.x = fmaxf(v1.x, 0.f); v1.y = fmaxf(v1.y, 0.f);
            }
            if (OMODE == 0) {
                *(float2*)&C[(size_t)m * N + n]       = v0;
                *(float2*)&C[(size_t)(m + 8) * N + n] = v1;
            } else {
                size_t o0 = ((size_t)(m >> 10) * NHEAD + (n >> 6)) * ((size_t)SEQ * DRED)
                          + (size_t)(m & (SEQ - 1)) * DRED + (n & 63);
                size_t o1 = ((size_t)((m + 8) >> 10) * NHEAD + (n >> 6)) * ((size_t)SEQ * DRED)
                          + (size_t)((m + 8) & (SEQ - 1)) * DRED + (n & 63);
                *(float2*)&C[o0] = v0;
                *(float2*)&C[o1] = v1;
            }
        }
    }
}

// ---------------------------------------------------------------------------
// Tensor-core flash attention (bf16 3-term hi/lo, exact online softmax).
// Q,K,V: [B,H,S,R] fp32.  Out: [B*S, H*R].
// Grid (S/128, B*H), 256 threads (8 warps x 16 query rows).
// smem: Q,K hi/lo [128 rows x 64 k], V hi/lo [128 k x 64 n]; pitch 144B.
// ---------------------------------------------------------------------------
#define APITCH 144
#define SQHI 0
#define SQLO 18432
#define SKHI 36864
#define SKLO 55296
#define SVHI 73728
#define SVLO 92160
#define ASMEM 110592

__global__ __launch_bounds__(256)
void attn_tc(const float* __restrict__ Q, const float* __restrict__ Kg,
             const float* __restrict__ Vg, float* __restrict__ Out)
{
    extern __shared__ char sm[];
    const uint32_t sb = smem_to_u32(sm);

    const int t    = threadIdx.x;
    const int lane = t & 31;
    const int w    = t >> 5;
    const int bh   = blockIdx.y;
    const int b    = bh >> 4;
    const int h    = bh & 15;
    const int q0   = blockIdx.x * 128;

    const size_t base = (size_t)bh * SEQ * DRED;
    const float* Qb = Q  + base;
    const float* Kb = Kg + base;
    const float* Vb = Vg + base;

    // staging role: thread t -> row t>>1 (0..127), half (t&1) (32 floats)
    const int lrow  = t >> 1;
    const int lhalf = t & 1;
    auto stage = [&](const float* src, uint32_t dhi, uint32_t dlo) {
        const float4* p = (const float4*)(src + (size_t)lrow * DRED + lhalf * 32);
        float4 f4[8];
        #pragma unroll
        for (int i = 0; i < 8; i++) f4[i] = p[i];
        uint32_t hp[16], lp[16];
        #pragma unroll
        for (int i = 0; i < 8; i++) {
            split2(f4[i].x, f4[i].y, hp[2*i],   lp[2*i]);
            split2(f4[i].z, f4[i].w, hp[2*i+1], lp[2*i+1]);
        }
        uint32_t off = (uint32_t)lrow * APITCH + lhalf * 64;
        #pragma unroll
        for (int i = 0; i < 4; i++) {
            *(uint4*)(sm + dhi + off + i*16) = make_uint4(hp[4*i], hp[4*i+1], hp[4*i+2], hp[4*i+3]);
            *(uint4*)(sm + dlo + off + i*16) = make_uint4(lp[4*i], lp[4*i+1], lp[4*i+2], lp[4*i+3]);
        }
    };

    // stage Q tile once
    stage(Qb + (size_t)q0 * DRED, SQHI, SQLO);

    // ldmatrix base addrs
    const uint32_t aOff = (uint32_t)(w * 16 + (lane & 15)) * APITCH + (lane >> 4) * 16;
    const uint32_t kRow = ((lane >> 4) << 3) + (lane & 7);
    const uint32_t kCol = ((lane >> 3) & 1) * 16;

    float S[16][4];
    float O[8][4];
    float m0 = -1e30f, m1 = -1e30f, l0 = 0.f, l1 = 0.f;
    #pragma unroll
    for (int j = 0; j < 8; j++)
        #pragma unroll
        for (int d = 0; d < 4; d++) O[j][d] = 0.f;

    for (int kt = 0; kt < SEQ / 128; kt++) {
        __syncthreads();   // previous iteration done reading K/V
        stage(Kb + (size_t)(kt * 128) * DRED, SKHI, SKLO);
        stage(Vb + (size_t)(kt * 128) * DRED, SVHI, SVLO);
        __syncthreads();

        // ---- S = Q K^T (3-term) ----
        #pragma unroll
        for (int j = 0; j < 16; j++) {
            S[j][0] = 0.f; S[j][1] = 0.f; S[j][2] = 0.f; S[j][3] = 0.f;
        }
        #pragma unroll
        for (int ks = 0; ks < 4; ks++) {
            uint32_t qh[4], ql[4];
            ldm_x4(qh, sb + SQHI + aOff + ks * 32);
            ldm_x4(ql, sb + SQLO + aOff + ks * 32);
            #pragma unroll
            for (int np = 0; np < 8; np++) {
                uint32_t off = (uint32_t)(np * 16 + kRow) * APITCH + kCol + ks * 32;
                uint32_t bh4[4], bl4[4];
                ldm_x4(bh4, sb + SKHI + off);
                ldm_x4(bl4, sb + SKLO + off);
                #pragma unroll
                for (int nt = 0; nt < 2; nt++) {
                    float* cc = S[np * 2 + nt];
                    mma_bf16(cc, qh, bh4[nt*2], bh4[nt*2+1]);
                    mma_bf16(cc, ql, bh4[nt*2], bh4[nt*2+1]);
                    mma_bf16(cc, qh, bl4[nt*2], bl4[nt*2+1]);
                }
            }
        }

        // ---- online softmax (rows r0 = lane>>2, r1 = r0+8) ----
        float mx0 = -1e30f, mx1 = -1e30f;
        #pragma unroll
        for (int j = 0; j < 16; j++) {
            S[j][0] *= 0.125f; S[j][1] *= 0.125f;
            S[j][2] *= 0.125f; S[j][3] *= 0.125f;
            mx0 = fmaxf(mx0, fmaxf(S[j][0], S[j][1]));
            mx1 = fmaxf(mx1, fmaxf(S[j][2], S[j][3]));
        }
        mx0 = fmaxf(mx0, __shfl_xor_sync(0xffffffffu, mx0, 1));
        mx0 = fmaxf(mx0, __shfl_xor_sync(0xffffffffu, mx0, 2));
        mx1 = fmaxf(mx1, __shfl_xor_sync(0xffffffffu, mx1, 1));
        mx1 = fmaxf(mx1, __shfl_xor_sync(0xffffffffu, mx1, 2));
        float mn0 = fmaxf(m0, mx0), mn1 = fmaxf(m1, mx1);
        float a0 = __expf(m0 - mn0), a1 = __expf(m1 - mn1);
        m0 = mn0; m1 = mn1;
        float rs0 = 0.f, rs1 = 0.f;
        #pragma unroll
        for (int j = 0; j < 16; j++) {
            float p0 = __expf(S[j][0] - mn0); S[j][0] = p0; rs0 += p0;
            float p1 = __expf(S[j][1] - mn0); S[j][1] = p1; rs0 += p1;
            float p2 = __expf(S[j][2] - mn1); S[j][2] = p2; rs1 += p2;
            float p3 = __expf(S[j][3] - mn1); S[j][3] = p3; rs1 += p3;
        }
        l0 = l0 * a0 + rs0;
        l1 = l1 * a1 + rs1;
        #pragma unroll
        for (int j = 0; j < 8; j++) {
            O[j][0] *= a0; O[j][1] *= a0;
            O[j][2] *= a1; O[j][3] *= a1;
        }

        // ---- O += P V (3-term) ----
        #pragma unroll
        for (int ks = 0; ks < 8; ks++) {
            uint32_t ah[4], al[4];
            split2(S[2*ks][0],   S[2*ks][1],   ah[0], al[0]);
            split2(S[2*ks][2],   S[2*ks][3],   ah[1], al[1]);
            split2(S[2*ks+1][0], S[2*ks+1][1], ah[2], al[2]);
            split2(S[2*ks+1][2], S[2*ks+1][3], ah[3], al[3]);
            #pragma unroll
            for (int np = 0; np < 4; np++) {
                // trans ldmatrix over V[k][n]: rows ks*16.., cols np*16..
                uint32_t off = (uint32_t)(ks * 16 + ((lane >> 3) & 1) * 8 + (lane & 7)) * APITCH
                             + (np * 16 + (lane >> 4) * 8) * 2;
                uint32_t bh4[4], bl4[4];
                ldm_x4_t(bh4, sb + SVHI + off);
                ldm_x4_t(bl4, sb + SVLO + off);
                #pragma unroll
                for (int nt = 0; nt < 2; nt++) {
                    float* cc = O[np * 2 + nt];
                    mma_bf16(cc, ah, bh4[nt*2], bh4[nt*2+1]);
                    mma_bf16(cc, al, bh4[nt*2], bh4[nt*2+1]);
                    mma_bf16(cc, ah, bl4[nt*2], bl4[nt*2+1]);
                }
            }
        }
    }

    // ---- finalize: reduce l across the 4 lanes of each row, normalize, write ----
    l0 += __shfl_xor_sync(0xffffffffu, l0, 1);
    l0 += __shfl_xor_sync(0xffffffffu, l0, 2);
    l1 += __shfl_xor_sync(0xffffffffu, l1, 1);
    l1 += __shfl_xor_sync(0xffffffffu, l1, 2);
    const float inv0 = 1.f / l0, inv1 = 1.f / l1;

    const int r0 = q0 + w * 16 + (lane >> 2);
    const size_t tok0 = (size_t)b * SEQ + r0;
    const size_t tok1 = tok0 + 8;
    #pragma unroll
    for (int ng = 0; ng < 8; ng++) {
        const int col = h * DRED + ng * 8 + (lane & 3) * 2;
        *(float2*)&Out[tok0 * DEMB + col] = make_float2(O[ng][0] * inv0, O[ng][1] * inv0);
        *(float2*)&Out[tok1 * DEMB + col] = make_float2(O[ng][2] * inv1, O[ng][3] * inv1);
    }
}

// ---------------------------------------------------------------------------
// LayerNorm over rows of 1024, eps = 1e-3
// ---------------------------------------------------------------------------
__global__ __launch_bounds__(256)
void ln_kernel(const float* __restrict__ in, const float* __restrict__ gam,
               const float* __restrict__ bet, float* __restrict__ out)
{
    __shared__ float red[16];
    const int row = blockIdx.x;
    const int t   = threadIdx.x;
    const float* p = in + (size_t)row * DEMB;

    float4 v = *(const float4*)&p[t * 4];
    float s  = v.x + v.y + v.z + v.w;
    float ss = v.x * v.x + v.y * v.y + v.z * v.z + v.w * v.w;
    #pragma unroll
    for (int o = 16; o >= 1; o >>= 1) {
        s  += __shfl_xor_sync(0xffffffffu, s, o);
        ss += __shfl_xor_sync(0xffffffffu, ss, o);
    }
    if ((t & 31) == 0) { red[t >> 5] = s; red[8 + (t >> 5)] = ss; }
    __syncthreads();
    s = 0.f; ss = 0.f;
    #pragma unroll
    for (int i = 0; i < 8; i++) { s += red[i]; ss += red[8 + i]; }

    float mean = s * (1.f / DEMB);
    float var  = ss * (1.f / DEMB) - mean * mean;
    float r    = rsqrtf(var + 1e-3f);

    float4 g4 = *(const float4*)&gam[t * 4];
    float4 b4 = *(const float4*)&bet[t * 4];
    float4 o;
    o.x = (v.x - mean) * r * g4.x + b4.x;
    o.y = (v.y - mean) * r * g4.y + b4.y;
    o.z = (v.z - mean) * r * g4.z + b4.z;
    o.w = (v.w - mean) * r * g4.w + b4.w;
    *(float4*)&out[(size_t)row * DEMB + t * 4] = o;
}

// ---------------------------------------------------------------------------
// Launch
// ---------------------------------------------------------------------------
extern "C" void kernel_launch(void* const* d_in, const int* in_sizes, int n_in,
                              void* d_out, int out_size)
{
    const float* x      = (const float*)d_in[0];
    const float* ctx    = (const float*)d_in[1];
    const float* sa_wq  = (const float*)d_in[2];
    const float* sa_bq  = (const float*)d_in[3];
    const float* sa_wk  = (const float*)d_in[4];
    const float* sa_bk  = (const float*)d_in[5];
    const float* sa_wv  = (const float*)d_in[6];
    const float* sa_bv  = (const float*)d_in[7];
    const float* sa_wo  = (const float*)d_in[8];
    const float* sa_bo  = (const float*)d_in[9];
    const float* ca_wq  = (const float*)d_in[10];
    const float* ca_bq  = (const float*)d_in[11];
    const float* ca_wk  = (const float*)d_in[12];
    const float* ca_bk  = (const float*)d_in[13];
    const float* ca_wv  = (const float*)d_in[14];
    const float* ca_bv  = (const float*)d_in[15];
    const float* ca_wo  = (const float*)d_in[16];
    const float* ca_bo  = (const float*)d_in[17];
    const float* ln1_g  = (const float*)d_in[18];
    const float* ln1_b  = (const float*)d_in[19];
    const float* ln2_g  = (const float*)d_in[20];
    const float* ln2_b  = (const float*)d_in[21];
    const float* ln3_g  = (const float*)d_in[22];
    const float* ln3_b  = (const float*)d_in[23];
    const float* ffn_w1 = (const float*)d_in[24];
    const float* ffn_b1 = (const float*)d_in[25];
    const float* ffn_w2 = (const float*)d_in[26];
    const float* ffn_b2 = (const float*)d_in[27];
    float* out = (float*)d_out;

    float *q, *k, *v, *att, *res, *ln1, *ln2, *ffn;
    __nv_bfloat16 *whi, *wlo;
    cudaGetSymbolAddress((void**)&q,   g_q);
    cudaGetSymbolAddress((void**)&k,   g_k);
    cudaGetSymbolAddress((void**)&v,   g_v);
    cudaGetSymbolAddress((void**)&att, g_att);
    cudaGetSymbolAddress((void**)&res, g_res);
    cudaGetSymbolAddress((void**)&ln1, g_ln1);
    cudaGetSymbolAddress((void**)&ln2, g_ln2);
    cudaGetSymbolAddress((void**)&ffn, g_ffn);
    cudaGetSymbolAddress((void**)&whi, g_whi);
    cudaGetSymbolAddress((void**)&wlo, g_wlo);

    cudaFuncSetAttribute(tgemm<1, false, false>, cudaFuncAttributeMaxDynamicSharedMemorySize, GSMEM);
    cudaFuncSetAttribute(tgemm<0, true,  false>, cudaFuncAttributeMaxDynamicSharedMemorySize, GSMEM);
    cudaFuncSetAttribute(tgemm<0, false, true >, cudaFuncAttributeMaxDynamicSharedMemorySize, GSMEM);
    cudaFuncSetAttribute(attn_tc, cudaFuncAttributeMaxDynamicSharedMemorySize, ASMEM);

    // ---- weight conversion ----
    dim3 tpP(2, 32, 16);
    wconv<<<tpP, 256>>>(sa_wq, whi + (size_t)0*WME, wlo + (size_t)0*WME, 1024, 64);
    wconv<<<tpP, 256>>>(sa_wk, whi + (size_t)1*WME, wlo + (size_t)1*WME, 1024, 64);
    wconv<<<tpP, 256>>>(sa_wv, whi + (size_t)2*WME, wlo + (size_t)2*WME, 1024, 64);
    dim3 tpO(32, 32, 1);
    wconv<<<tpO, 256>>>(sa_wo, whi + (size_t)3*WME, wlo + (size_t)3*WME, 1024, 1024);
    wconv<<<tpP, 256>>>(ca_wq, whi + (size_t)4*WME, wlo + (size_t)4*WME, 1024, 64);
    wconv<<<tpP, 256>>>(ca_wk, whi + (size_t)5*WME, wlo + (size_t)5*WME, 1024, 64);
    wconv<<<tpP, 256>>>(ca_wv, whi + (size_t)6*WME, wlo + (size_t)6*WME, 1024, 64);
    wconv<<<tpO, 256>>>(ca_wo, whi + (size_t)7*WME, wlo + (size_t)7*WME, 1024, 1024);
    dim3 tpF1(128, 32, 1);
    wconv<<<tpF1, 256>>>(ffn_w1, whi + (size_t)8*WME,  wlo + (size_t)8*WME,  1024, 4096);
    dim3 tpF2(32, 128, 1);
    wconv<<<tpF2, 256>>>(ffn_w2, whi + (size_t)12*WME, wlo + (size_t)12*WME, 4096, 1024);

    dim3 gProj(DEMB / 128, NTOK / 128);    // (8, 32)
    dim3 gFfn1(DFFN / 128, NTOK / 128);    // (32, 32)
    dim3 gAttn(SEQ / 128, BQ * NHEAD);     // (8, 64)

    // ---- self attention ----
    tgemm<1, false, false><<<gProj, 256, GSMEM>>>(x, whi + 0*WME, wlo + 0*WME, sa_bq, nullptr, q, NTOK, DEMB, DEMB);
    tgemm<1, false, false><<<gProj, 256, GSMEM>>>(x, whi + 1*WME, wlo + 1*WME, sa_bk, nullptr, k, NTOK, DEMB, DEMB);
    tgemm<1, false, false><<<gProj, 256, GSMEM>>>(x, whi + 2*WME, wlo + 2*WME, sa_bv, nullptr, v, NTOK, DEMB, DEMB);
    attn_tc<<<gAttn, 256, ASMEM>>>(q, k, v, att);
    tgemm<0, true, false><<<gProj, 256, GSMEM>>>(att, whi + 3*WME, wlo + 3*WME, sa_bo, x, res, NTOK, DEMB, DEMB);
    ln_kernel<<<NTOK, 256>>>(res, ln1_g, ln1_b, ln1);

    // ---- cross attention ----
    tgemm<1, false, false><<<gProj, 256, GSMEM>>>(ln1, whi + 4*WME, wlo + 4*WME, ca_bq, nullptr, q, NTOK, DEMB, DEMB);
    tgemm<1, false, false><<<gProj, 256, GSMEM>>>(ctx, whi + 5*WME, wlo + 5*WME, ca_bk, nullptr, k, NTOK, DEMB, DEMB);
    tgemm<1, false, false><<<gProj, 256, GSMEM>>>(ctx, whi + 6*WME, wlo + 6*WME, ca_bv, nullptr, v, NTOK, DEMB, DEMB);
    attn_tc<<<gAttn, 256, ASMEM>>>(q, k, v, att);
    tgemm<0, true, false><<<gProj, 256, GSMEM>>>(att, whi + 7*WME, wlo + 7*WME, ca_bo, ln1, res, NTOK, DEMB, DEMB);
    ln_kernel<<<NTOK, 256>>>(res, ln2_g, ln2_b, ln2);

    // ---- FFN ----
    tgemm<0, false, true><<<gFfn1, 256, GSMEM>>>(ln2, whi + (size_t)8*WME, wlo + (size_t)8*WME, ffn_b1, nullptr, ffn, NTOK, DFFN, DEMB);
    tgemm<0, true, false><<<gProj, 256, GSMEM>>>(ffn, whi + (size_t)12*WME, wlo + (size_t)12*WME, ffn_b2, ln2, res, NTOK, DEMB, DFFN);
    ln_kernel<<<NTOK, 256>>>(res, ln3_g, ln3_b, out);
}

// round 7
// speedup vs baseline: 3.5356x; 1.7082x over previous
#include <cuda_runtime.h>
#include <cuda_fp16.h>
#include <cstdint>
#include <cstddef>

// Problem constants
#define BQ 4
#define SEQ 1024
#define DEMB 1024
#define NHEAD 16
#define DRED 64
#define NTOK (BQ*SEQ)          // 4096
#define DFFN (4*DEMB)          // 4096

// ---------------------------------------------------------------------------
// Scratch (static device memory; no allocations anywhere)
// ---------------------------------------------------------------------------
__device__ float g_q  [(size_t)BQ*NHEAD*SEQ*DRED];
__device__ float g_k  [(size_t)BQ*NHEAD*SEQ*DRED];
__device__ float g_v  [(size_t)BQ*NHEAD*SEQ*DRED];
__device__ float g_att[(size_t)NTOK*DEMB];
__device__ float g_res[(size_t)NTOK*DEMB];
__device__ float g_ln1[(size_t)NTOK*DEMB];
__device__ float g_ln2[(size_t)NTOK*DEMB];
__device__ float g_ffn[(size_t)NTOK*DFFN];

// fp16 weight scratch: transposed [N,K].
//  offsets (units of 1M elements):
//  0:sa_wq 1:sa_wk 2:sa_wv 3:sa_wo 4:ca_wq 5:ca_wk 6:ca_wv 7:ca_wo
//  8..11: ffn_w1 (4M)   12..15: ffn_w2 (4M)
#define WME (1024*1024)
__device__ __half g_wh[(size_t)16*WME];

// ---------------------------------------------------------------------------
// PTX helpers (baseline PTX only)
// ---------------------------------------------------------------------------
__device__ __forceinline__ uint32_t smem_to_u32(const void* p) {
    uint32_t a;
    asm("{ .reg .u64 t; cvta.to.shared.u64 t, %1; cvt.u32.u64 %0, t; }"
        : "=r"(a) : "l"(p));
    return a;
}
__device__ __forceinline__ void cp_async16(uint32_t s, const void* g) {
    asm volatile("cp.async.cg.shared.global [%0], [%1], 16;" :: "r"(s), "l"(g));
}
#define CP_COMMIT() asm volatile("cp.async.commit_group;" ::: "memory")
#define CP_WAIT0()  asm volatile("cp.async.wait_group 0;" ::: "memory")

__device__ __forceinline__ void ldm_x4(uint32_t* r, uint32_t addr) {
    asm volatile("ldmatrix.sync.aligned.m8n8.x4.shared.b16 {%0,%1,%2,%3}, [%4];"
        : "=r"(r[0]), "=r"(r[1]), "=r"(r[2]), "=r"(r[3]) : "r"(addr));
}
__device__ __forceinline__ void ldm_x4_t(uint32_t* r, uint32_t addr) {
    asm volatile("ldmatrix.sync.aligned.m8n8.x4.trans.shared.b16 {%0,%1,%2,%3}, [%4];"
        : "=r"(r[0]), "=r"(r[1]), "=r"(r[2]), "=r"(r[3]) : "r"(addr));
}
__device__ __forceinline__ void mma_f16(float* c, const uint32_t* a,
                                        uint32_t b0, uint32_t b1) {
    asm volatile(
        "mma.sync.aligned.m16n8k16.row.col.f32.f16.f16.f32 "
        "{%0,%1,%2,%3}, {%4,%5,%6,%7}, {%8,%9}, {%0,%1,%2,%3};"
        : "+f"(c[0]), "+f"(c[1]), "+f"(c[2]), "+f"(c[3])
        : "r"(a[0]), "r"(a[1]), "r"(a[2]), "r"(a[3]), "r"(b0), "r"(b1));
}
__device__ __forceinline__ uint32_t pack_h2(float x, float y) {
    __half2 h = __floats2half2_rn(x, y);
    return *(uint32_t*)&h;
}

// ---------------------------------------------------------------------------
// Weight transpose + fp16 convert.
// Input block z: in + z*R*C, [R,C] row-major fp32.
// Output row n = z*C + c (length R): out[n*R + r] = in[z][r][c].
// ---------------------------------------------------------------------------
__global__ __launch_bounds__(256)
void wconv(const float* __restrict__ in, __half* __restrict__ oh, int R, int C)
{
    __shared__ float tile[32][33];
    const int bz = blockIdx.z;
    const float* ip = in + (size_t)bz * R * C;
    const int r0 = blockIdx.y * 32, c0 = blockIdx.x * 32;
    const int tx = threadIdx.x & 31;
    const int ty = threadIdx.x >> 5;

    #pragma unroll
    for (int i = 0; i < 32; i += 8)
        tile[ty + i][tx] = ip[(size_t)(r0 + ty + i) * C + c0 + tx];
    __syncthreads();

    #pragma unroll
    for (int i = 0; i < 32; i += 8) {
        float x = tile[tx][ty + i];
        size_t o = ((size_t)bz * C + c0 + ty + i) * R + r0 + tx;
        oh[o] = __float2half_rn(x);
    }
}

// ---------------------------------------------------------------------------
// Tensor-core GEMM via mma.sync (fp16, single term, fp32 accumulate).
// C[M,N] = A[M,K](fp32) * W[N,K]^T  (+bias) (+resid) (relu?)
// CTA 128x128, BK=32, double-buffered smem, cp.async weights.
// smem row pitch 80B (64B data + 16B pad -> conflict-free ldmatrix).
//  OMODE 0: C row-major [M,N];  OMODE 1: C in [B,H,S,R] (m=b*S+s, n=h*64+r)
// ---------------------------------------------------------------------------
#define PITCH 80
#define OFF_W  10240
#define BUFSZ  20480
#define GSMEM  (2*BUFSZ)

template<int OMODE, bool RESID, bool RELU>
__global__ __launch_bounds__(256)
void tgemm(const float* __restrict__ A, const __half* __restrict__ W,
           const float* __restrict__ bias, const float* __restrict__ resid,
           float* __restrict__ C, int M, int N, int K)
{
    extern __shared__ char smem[];
    const uint32_t sb = smem_to_u32(smem);

    const int t    = threadIdx.x;
    const int lane = t & 31;
    const int wid  = t >> 5;
    const int wm   = wid & 3;
    const int wn   = wid >> 2;
    const int m0   = blockIdx.y * 128;
    const int n0   = blockIdx.x * 128;
    const int nch  = K >> 5;

    const int arow  = t >> 1;
    const int akoff = (t & 1) * 16;
    const uint32_t aStOff = (uint32_t)arow * PITCH + (t & 1) * 32;

    const int q0r = (2 * t) >> 2,     q0c = (2 * t) & 3;
    const int q1r = (2 * t + 1) >> 2, q1c = (2 * t + 1) & 3;

    float acc[2][8][4];
    #pragma unroll
    for (int a = 0; a < 2; a++)
        #pragma unroll
        for (int b = 0; b < 8; b++)
            #pragma unroll
            for (int d = 0; d < 4; d++) acc[a][b][d] = 0.f;

    auto loadW = [&](int k0, uint32_t bufo) {
        cp_async16(sb + bufo + OFF_W + q0r * PITCH + q0c * 16,
                   W + (size_t)(n0 + q0r) * K + k0 + q0c * 8);
        cp_async16(sb + bufo + OFF_W + q1r * PITCH + q1c * 16,
                   W + (size_t)(n0 + q1r) * K + k0 + q1c * 8);
        CP_COMMIT();
    };
    auto loadA = [&](int k0, float4* f4) {
        const float4* ap = (const float4*)(A + (size_t)(m0 + arow) * K + k0 + akoff);
        #pragma unroll
        for (int i = 0; i < 4; i++) f4[i] = ap[i];
    };
    auto storeA = [&](const float4* f4, uint32_t bufo) {
        uint32_t hp[8];
        #pragma unroll
        for (int i = 0; i < 4; i++) {
            hp[2*i]   = pack_h2(f4[i].x, f4[i].y);
            hp[2*i+1] = pack_h2(f4[i].z, f4[i].w);
        }
        *(uint4*)(smem + bufo + aStOff)      = make_uint4(hp[0], hp[1], hp[2], hp[3]);
        *(uint4*)(smem + bufo + aStOff + 16) = make_uint4(hp[4], hp[5], hp[6], hp[7]);
    };

    const uint32_t aBase = sb + (uint32_t)(wm * 32 + (lane & 15)) * PITCH + (lane >> 4) * 16;
    const uint32_t wBase = sb + OFF_W
        + (uint32_t)(wn * 64 + ((lane >> 4) << 3) + (lane & 7)) * PITCH
        + ((lane >> 3) & 1) * 16;

    auto compute = [&](uint32_t bufo) {
        #pragma unroll
        for (int ks = 0; ks < 2; ks++) {
            uint32_t ah[2][4];
            #pragma unroll
            for (int mt = 0; mt < 2; mt++)
                ldm_x4(ah[mt], aBase + bufo + mt * (16*PITCH) + ks * 32);
            #pragma unroll
            for (int ng = 0; ng < 2; ng++) {
                uint32_t bh[8];
                #pragma unroll
                for (int p = 0; p < 2; p++)
                    ldm_x4(bh + p*4, wBase + bufo + (ng*2 + p) * (16*PITCH) + ks * 32);
                #pragma unroll
                for (int nt = 0; nt < 4; nt++)
                    #pragma unroll
                    for (int mt = 0; mt < 2; mt++)
                        mma_f16(acc[mt][ng*4 + nt], ah[mt], bh[nt*2], bh[nt*2+1]);
            }
        }
    };

    {
        loadW(0, 0);
        float4 f4[4];
        loadA(0, f4);
        storeA(f4, 0);
        CP_WAIT0();
        __syncthreads();
    }

    for (int c = 0; c < nch; c++) {
        const uint32_t bufo  = (c & 1) * BUFSZ;
        const uint32_t nbufo = BUFSZ - bufo;
        const bool hasNext = (c + 1 < nch);
        float4 f4[4];
        if (hasNext) {
            loadW((c + 1) << 5, nbufo);
            loadA((c + 1) << 5, f4);
        }
        compute(bufo);
        if (hasNext) {
            storeA(f4, nbufo);
            CP_WAIT0();
        }
        __syncthreads();
    }

    #pragma unroll
    for (int mt = 0; mt < 2; mt++) {
        const int m = m0 + wm * 32 + mt * 16 + (lane >> 2);
        #pragma unroll
        for (int j = 0; j < 8; j++) {
            const int n = n0 + wn * 64 + j * 8 + (lane & 3) * 2;
            float2 v0 = make_float2(acc[mt][j][0], acc[mt][j][1]);
            float2 v1 = make_float2(acc[mt][j][2], acc[mt][j][3]);
            float2 b2 = *(const float2*)&bias[n];
            v0.x += b2.x; v0.y += b2.y;
            v1.x += b2.x; v1.y += b2.y;
            if (RESID) {
                float2 r0 = *(const float2*)&resid[(size_t)m * N + n];
                float2 r1 = *(const float2*)&resid[(size_t)(m + 8) * N + n];
                v0.x += r0.x; v0.y += r0.y;
                v1.x += r1.x; v1.y += r1.y;
            }
            if (RELU) {
                v0.x = fmaxf(v0.x, 0.f); v0.y = fmaxf(v0.y, 0.f);
                v1.x = fmaxf(v1.x, 0.f); v1.y = fmaxf(v1.y, 0.f);
            }
            if (OMODE == 0) {
                *(float2*)&C[(size_t)m * N + n]       = v0;
                *(float2*)&C[(size_t)(m + 8) * N + n] = v1;
            } else {
                size_t o0 = ((size_t)(m >> 10) * NHEAD + (n >> 6)) * ((size_t)SEQ * DRED)
                          + (size_t)(m & (SEQ - 1)) * DRED + (n & 63);
                size_t o1 = ((size_t)((m + 8) >> 10) * NHEAD + (n >> 6)) * ((size_t)SEQ * DRED)
                          + (size_t)((m + 8) & (SEQ - 1)) * DRED + (n & 63);
                *(float2*)&C[o0] = v0;
                *(float2*)&C[o1] = v1;
            }
        }
    }
}

// ---------------------------------------------------------------------------
// Tensor-core flash attention (fp16 single term, exact online softmax).
// Q,K,V: [B,H,S,R] fp32.  Out: [B*S, H*R].
// Grid (S/128, B*H), 256 threads (8 warps x 16 query rows).
// smem: Q,K [128 rows x 64 k fp16], V [128 k x 64 n fp16]; pitch 144B.
// ---------------------------------------------------------------------------
#define APITCH 144
#define SQ_OFF 0
#define SK_OFF 18432
#define SV_OFF 36864
#define ASMEM  55296

__global__ __launch_bounds__(256)
void attn_tc(const float* __restrict__ Q, const float* __restrict__ Kg,
             const float* __restrict__ Vg, float* __restrict__ Out)
{
    extern __shared__ char sm[];
    const uint32_t sb = smem_to_u32(sm);

    const int t    = threadIdx.x;
    const int lane = t & 31;
    const int w    = t >> 5;
    const int bh   = blockIdx.y;
    const int b    = bh >> 4;
    const int h    = bh & 15;
    const int q0   = blockIdx.x * 128;

    const size_t base = (size_t)bh * SEQ * DRED;
    const float* Qb = Q  + base;
    const float* Kb = Kg + base;
    const float* Vb = Vg + base;

    // staging role: thread t -> row t>>1 (0..127), half (t&1) (32 floats)
    const int lrow  = t >> 1;
    const int lhalf = t & 1;
    auto stage = [&](const float* src, uint32_t dst) {
        const float4* p = (const float4*)(src + (size_t)lrow * DRED + lhalf * 32);
        float4 f4[8];
        #pragma unroll
        for (int i = 0; i < 8; i++) f4[i] = p[i];
        uint32_t hp[16];
        #pragma unroll
        for (int i = 0; i < 8; i++) {
            hp[2*i]   = pack_h2(f4[i].x, f4[i].y);
            hp[2*i+1] = pack_h2(f4[i].z, f4[i].w);
        }
        uint32_t off = (uint32_t)lrow * APITCH + lhalf * 64;
        #pragma unroll
        for (int i = 0; i < 4; i++)
            *(uint4*)(sm + dst + off + i*16) = make_uint4(hp[4*i], hp[4*i+1], hp[4*i+2], hp[4*i+3]);
    };

    // stage Q tile once
    stage(Qb + (size_t)q0 * DRED, SQ_OFF);

    const uint32_t aOff = (uint32_t)(w * 16 + (lane & 15)) * APITCH + (lane >> 4) * 16;
    const uint32_t kRow = ((lane >> 4) << 3) + (lane & 7);
    const uint32_t kCol = ((lane >> 3) & 1) * 16;

    float S[16][4];
    float O[8][4];
    float m0 = -1e30f, m1 = -1e30f, l0 = 0.f, l1 = 0.f;
    #pragma unroll
    for (int j = 0; j < 8; j++)
        #pragma unroll
        for (int d = 0; d < 4; d++) O[j][d] = 0.f;

    for (int kt = 0; kt < SEQ / 128; kt++) {
        __syncthreads();
        stage(Kb + (size_t)(kt * 128) * DRED, SK_OFF);
        stage(Vb + (size_t)(kt * 128) * DRED, SV_OFF);
        __syncthreads();

        // ---- S = Q K^T ----
        #pragma unroll
        for (int j = 0; j < 16; j++) {
            S[j][0] = 0.f; S[j][1] = 0.f; S[j][2] = 0.f; S[j][3] = 0.f;
        }
        #pragma unroll
        for (int ks = 0; ks < 4; ks++) {
            uint32_t qh[4];
            ldm_x4(qh, sb + SQ_OFF + aOff + ks * 32);
            #pragma unroll
            for (int np = 0; np < 8; np++) {
                uint32_t off = (uint32_t)(np * 16 + kRow) * APITCH + kCol + ks * 32;
                uint32_t bh4[4];
                ldm_x4(bh4, sb + SK_OFF + off);
                #pragma unroll
                for (int nt = 0; nt < 2; nt++)
                    mma_f16(S[np * 2 + nt], qh, bh4[nt*2], bh4[nt*2+1]);
            }
        }

        // ---- online softmax (rows r0 = lane>>2, r1 = r0+8) ----
        float mx0 = -1e30f, mx1 = -1e30f;
        #pragma unroll
        for (int j = 0; j < 16; j++) {
            S[j][0] *= 0.125f; S[j][1] *= 0.125f;
            S[j][2] *= 0.125f; S[j][3] *= 0.125f;
            mx0 = fmaxf(mx0, fmaxf(S[j][0], S[j][1]));
            mx1 = fmaxf(mx1, fmaxf(S[j][2], S[j][3]));
        }
        mx0 = fmaxf(mx0, __shfl_xor_sync(0xffffffffu, mx0, 1));
        mx0 = fmaxf(mx0, __shfl_xor_sync(0xffffffffu, mx0, 2));
        mx1 = fmaxf(mx1, __shfl_xor_sync(0xffffffffu, mx1, 1));
        mx1 = fmaxf(mx1, __shfl_xor_sync(0xffffffffu, mx1, 2));
        float mn0 = fmaxf(m0, mx0), mn1 = fmaxf(m1, mx1);
        float a0 = __expf(m0 - mn0), a1 = __expf(m1 - mn1);
        m0 = mn0; m1 = mn1;
        float rs0 = 0.f, rs1 = 0.f;
        #pragma unroll
        for (int j = 0; j < 16; j++) {
            float p0 = __expf(S[j][0] - mn0); S[j][0] = p0; rs0 += p0;
            float p1 = __expf(S[j][1] - mn0); S[j][1] = p1; rs0 += p1;
            float p2 = __expf(S[j][2] - mn1); S[j][2] = p2; rs1 += p2;
            float p3 = __expf(S[j][3] - mn1); S[j][3] = p3; rs1 += p3;
        }
        l0 = l0 * a0 + rs0;
        l1 = l1 * a1 + rs1;
        #pragma unroll
        for (int j = 0; j < 8; j++) {
            O[j][0] *= a0; O[j][1] *= a0;
            O[j][2] *= a1; O[j][3] *= a1;
        }

        // ---- O += P V ----
        #pragma unroll
        for (int ks = 0; ks < 8; ks++) {
            uint32_t ah[4];
            ah[0] = pack_h2(S[2*ks][0],   S[2*ks][1]);
            ah[1] = pack_h2(S[2*ks][2],   S[2*ks][3]);
            ah[2] = pack_h2(S[2*ks+1][0], S[2*ks+1][1]);
            ah[3] = pack_h2(S[2*ks+1][2], S[2*ks+1][3]);
            #pragma unroll
            for (int np = 0; np < 4; np++) {
                uint32_t off = (uint32_t)(ks * 16 + ((lane >> 3) & 1) * 8 + (lane & 7)) * APITCH
                             + (np * 16 + (lane >> 4) * 8) * 2;
                uint32_t bh4[4];
                ldm_x4_t(bh4, sb + SV_OFF + off);
                #pragma unroll
                for (int nt = 0; nt < 2; nt++)
                    mma_f16(O[np * 2 + nt], ah, bh4[nt*2], bh4[nt*2+1]);
            }
        }
    }

    // ---- finalize ----
    l0 += __shfl_xor_sync(0xffffffffu, l0, 1);
    l0 += __shfl_xor_sync(0xffffffffu, l0, 2);
    l1 += __shfl_xor_sync(0xffffffffu, l1, 1);
    l1 += __shfl_xor_sync(0xffffffffu, l1, 2);
    const float inv0 = 1.f / l0, inv1 = 1.f / l1;

    const int r0 = q0 + w * 16 + (lane >> 2);
    const size_t tok0 = (size_t)b * SEQ + r0;
    const size_t tok1 = tok0 + 8;
    #pragma unroll
    for (int ng = 0; ng < 8; ng++) {
        const int col = h * DRED + ng * 8 + (lane & 3) * 2;
        *(float2*)&Out[tok0 * DEMB + col] = make_float2(O[ng][0] * inv0, O[ng][1] * inv0);
        *(float2*)&Out[tok1 * DEMB + col] = make_float2(O[ng][2] * inv1, O[ng][3] * inv1);
    }
}

// ---------------------------------------------------------------------------
// LayerNorm over rows of 1024, eps = 1e-3
// ---------------------------------------------------------------------------
__global__ __launch_bounds__(256)
void ln_kernel(const float* __restrict__ in, const float* __restrict__ gam,
               const float* __restrict__ bet, float* __restrict__ out)
{
    __shared__ float red[16];
    const int row = blockIdx.x;
    const int t   = threadIdx.x;
    const float* p = in + (size_t)row * DEMB;

    float4 v = *(const float4*)&p[t * 4];
    float s  = v.x + v.y + v.z + v.w;
    float ss = v.x * v.x + v.y * v.y + v.z * v.z + v.w * v.w;
    #pragma unroll
    for (int o = 16; o >= 1; o >>= 1) {
        s  += __shfl_xor_sync(0xffffffffu, s, o);
        ss += __shfl_xor_sync(0xffffffffu, ss, o);
    }
    if ((t & 31) == 0) { red[t >> 5] = s; red[8 + (t >> 5)] = ss; }
    __syncthreads();
    s = 0.f; ss = 0.f;
    #pragma unroll
    for (int i = 0; i < 8; i++) { s += red[i]; ss += red[8 + i]; }

    float mean = s * (1.f / DEMB);
    float var  = ss * (1.f / DEMB) - mean * mean;
    float r    = rsqrtf(var + 1e-3f);

    float4 g4 = *(const float4*)&gam[t * 4];
    float4 b4 = *(const float4*)&bet[t * 4];
    float4 o;
    o.x = (v.x - mean) * r * g4.x + b4.x;
    o.y = (v.y - mean) * r * g4.y + b4.y;
    o.z = (v.z - mean) * r * g4.z + b4.z;
    o.w = (v.w - mean) * r * g4.w + b4.w;
    *(float4*)&out[(size_t)row * DEMB + t * 4] = o;
}

// ---------------------------------------------------------------------------
// Launch
// ---------------------------------------------------------------------------
extern "C" void kernel_launch(void* const* d_in, const int* in_sizes, int n_in,
                              void* d_out, int out_size)
{
    const float* x      = (const float*)d_in[0];
    const float* ctx    = (const float*)d_in[1];
    const float* sa_wq  = (const float*)d_in[2];
    const float* sa_bq  = (const float*)d_in[3];
    const float* sa_wk  = (const float*)d_in[4];
    const float* sa_bk  = (const float*)d_in[5];
    const float* sa_wv  = (const float*)d_in[6];
    const float* sa_bv  = (const float*)d_in[7];
    const float* sa_wo  = (const float*)d_in[8];
    const float* sa_bo  = (const float*)d_in[9];
    const float* ca_wq  = (const float*)d_in[10];
    const float* ca_bq  = (const float*)d_in[11];
    const float* ca_wk  = (const float*)d_in[12];
    const float* ca_bk  = (const float*)d_in[13];
    const float* ca_wv  = (const float*)d_in[14];
    const float* ca_bv  = (const float*)d_in[15];
    const float* ca_wo  = (const float*)d_in[16];
    const float* ca_bo  = (const float*)d_in[17];
    const float* ln1_g  = (const float*)d_in[18];
    const float* ln1_b  = (const float*)d_in[19];
    const float* ln2_g  = (const float*)d_in[20];
    const float* ln2_b  = (const float*)d_in[21];
    const float* ln3_g  = (const float*)d_in[22];
    const float* ln3_b  = (const float*)d_in[23];
    const float* ffn_w1 = (const float*)d_in[24];
    const float* ffn_b1 = (const float*)d_in[25];
    const float* ffn_w2 = (const float*)d_in[26];
    const float* ffn_b2 = (const float*)d_in[27];
    float* out = (float*)d_out;

    float *q, *k, *v, *att, *res, *ln1, *ln2, *ffn;
    __half *wh;
    cudaGetSymbolAddress((void**)&q,   g_q);
    cudaGetSymbolAddress((void**)&k,   g_k);
    cudaGetSymbolAddress((void**)&v,   g_v);
    cudaGetSymbolAddress((void**)&att, g_att);
    cudaGetSymbolAddress((void**)&res, g_res);
    cudaGetSymbolAddress((void**)&ln1, g_ln1);
    cudaGetSymbolAddress((void**)&ln2, g_ln2);
    cudaGetSymbolAddress((void**)&ffn, g_ffn);
    cudaGetSymbolAddress((void**)&wh,  g_wh);

    cudaFuncSetAttribute(tgemm<1, false, false>, cudaFuncAttributeMaxDynamicSharedMemorySize, GSMEM);
    cudaFuncSetAttribute(tgemm<0, true,  false>, cudaFuncAttributeMaxDynamicSharedMemorySize, GSMEM);
    cudaFuncSetAttribute(tgemm<0, false, true >, cudaFuncAttributeMaxDynamicSharedMemorySize, GSMEM);
    cudaFuncSetAttribute(attn_tc, cudaFuncAttributeMaxDynamicSharedMemorySize, ASMEM);

    // ---- weight conversion: transpose + fp16 ----
    dim3 tpP(2, 32, 16);
    wconv<<<tpP, 256>>>(sa_wq, wh + (size_t)0*WME, 1024, 64);
    wconv<<<tpP, 256>>>(sa_wk, wh + (size_t)1*WME, 1024, 64);
    wconv<<<tpP, 256>>>(sa_wv, wh + (size_t)2*WME, 1024, 64);
    dim3 tpO(32, 32, 1);
    wconv<<<tpO, 256>>>(sa_wo, wh + (size_t)3*WME, 1024, 1024);
    wconv<<<tpP, 256>>>(ca_wq, wh + (size_t)4*WME, 1024, 64);
    wconv<<<tpP, 256>>>(ca_wk, wh + (size_t)5*WME, 1024, 64);
    wconv<<<tpP, 256>>>(ca_wv, wh + (size_t)6*WME, 1024, 64);
    wconv<<<tpO, 256>>>(ca_wo, wh + (size_t)7*WME, 1024, 1024);
    dim3 tpF1(128, 32, 1);
    wconv<<<tpF1, 256>>>(ffn_w1, wh + (size_t)8*WME,  1024, 4096);
    dim3 tpF2(32, 128, 1);
    wconv<<<tpF2, 256>>>(ffn_w2, wh + (size_t)12*WME, 4096, 1024);

    dim3 gProj(DEMB / 128, NTOK / 128);    // (8, 32)
    dim3 gFfn1(DFFN / 128, NTOK / 128);    // (32, 32)
    dim3 gAttn(SEQ / 128, BQ * NHEAD);     // (8, 64)

    // ---- self attention ----
    tgemm<1, false, false><<<gProj, 256, GSMEM>>>(x, wh + 0*WME, sa_bq, nullptr, q, NTOK, DEMB, DEMB);
    tgemm<1, false, false><<<gProj, 256, GSMEM>>>(x, wh + 1*WME, sa_bk, nullptr, k, NTOK, DEMB, DEMB);
    tgemm<1, false, false><<<gProj, 256, GSMEM>>>(x, wh + 2*WME, sa_bv, nullptr, v, NTOK, DEMB, DEMB);
    attn_tc<<<gAttn, 256, ASMEM>>>(q, k, v, att);
    tgemm<0, true, false><<<gProj, 256, GSMEM>>>(att, wh + 3*WME, sa_bo, x, res, NTOK, DEMB, DEMB);
    ln_kernel<<<NTOK, 256>>>(res, ln1_g, ln1_b, ln1);

    // ---- cross attention ----
    tgemm<1, false, false><<<gProj, 256, GSMEM>>>(ln1, wh + 4*WME, ca_bq, nullptr, q, NTOK, DEMB, DEMB);
    tgemm<1, false, false><<<gProj, 256, GSMEM>>>(ctx, wh + 5*WME, ca_bk, nullptr, k, NTOK, DEMB, DEMB);
    tgemm<1, false, false><<<gProj, 256, GSMEM>>>(ctx, wh + 6*WME, ca_bv, nullptr, v, NTOK, DEMB, DEMB);
    attn_tc<<<gAttn, 256, ASMEM>>>(q, k, v, att);
    tgemm<0, true, false><<<gProj, 256, GSMEM>>>(att, wh + 7*WME, ca_bo, ln1, res, NTOK, DEMB, DEMB);
    ln_kernel<<<NTOK, 256>>>(res, ln2_g, ln2_b, ln2);

    // ---- FFN ----
    tgemm<0, false, true><<<gFfn1, 256, GSMEM>>>(ln2, wh + (size_t)8*WME, ffn_b1, nullptr, ffn, NTOK, DFFN, DEMB);
    tgemm<0, true, false><<<gProj, 256, GSMEM>>>(ffn, wh + (size_t)12*WME, ffn_b2, ln2, res, NTOK, DEMB, DFFN);
    ln_kernel<<<NTOK, 256>>>(res, ln3_g, ln3_b, out);
}

// round 8
// speedup vs baseline: 5.1398x; 1.4537x over previous
#include <cuda_runtime.h>
#include <cuda_fp16.h>
#include <cstdint>
#include <cstddef>

// Problem constants
#define BQ 4
#define SEQ 1024
#define DEMB 1024
#define NHEAD 16
#define DRED 64
#define NTOK (BQ*SEQ)          // 4096
#define DFFN (4*DEMB)          // 4096
#define BHSR ((size_t)BQ*NHEAD*SEQ*DRED)   // 4M

// ---------------------------------------------------------------------------
// Scratch (static device memory; no allocations anywhere)
// ---------------------------------------------------------------------------
__device__ float  g_res [(size_t)NTOK*DEMB];
__device__ float  g_ln1 [(size_t)NTOK*DEMB];
__device__ float  g_ln2 [(size_t)NTOK*DEMB];
__device__ __half g_xh  [(size_t)NTOK*DEMB];
__device__ __half g_ctxh[(size_t)NTOK*DEMB];
__device__ __half g_ln1h[(size_t)NTOK*DEMB];
__device__ __half g_ln2h[(size_t)NTOK*DEMB];
__device__ __half g_atth[(size_t)NTOK*DEMB];
__device__ __half g_ffnh[(size_t)NTOK*DFFN];
__device__ __half g_qkvh[(size_t)3*BHSR];

// fp16 weight scratch: transposed [N,K].
//  offsets (units of 1M elements): 0..2 sa_wq/wk/wv, 3 sa_wo, 4..6 ca_wq/wk/wv,
//  7 ca_wo, 8..11 ffn_w1, 12..15 ffn_w2
#define WME (1024*1024)
__device__ __half g_wh[(size_t)16*WME];

// ---------------------------------------------------------------------------
// PTX helpers (baseline PTX only)
// ---------------------------------------------------------------------------
__device__ __forceinline__ uint32_t smem_to_u32(const void* p) {
    uint32_t a;
    asm("{ .reg .u64 t; cvta.to.shared.u64 t, %1; cvt.u32.u64 %0, t; }"
        : "=r"(a) : "l"(p));
    return a;
}
__device__ __forceinline__ void cp_async16(uint32_t s, const void* g) {
    asm volatile("cp.async.cg.shared.global [%0], [%1], 16;" :: "r"(s), "l"(g));
}
#define CP_COMMIT() asm volatile("cp.async.commit_group;" ::: "memory")
#define CP_WAIT0()  asm volatile("cp.async.wait_group 0;" ::: "memory")

__device__ __forceinline__ void ldm_x4(uint32_t* r, uint32_t addr) {
    asm volatile("ldmatrix.sync.aligned.m8n8.x4.shared.b16 {%0,%1,%2,%3}, [%4];"
        : "=r"(r[0]), "=r"(r[1]), "=r"(r[2]), "=r"(r[3]) : "r"(addr));
}
__device__ __forceinline__ void ldm_x4_t(uint32_t* r, uint32_t addr) {
    asm volatile("ldmatrix.sync.aligned.m8n8.x4.trans.shared.b16 {%0,%1,%2,%3}, [%4];"
        : "=r"(r[0]), "=r"(r[1]), "=r"(r[2]), "=r"(r[3]) : "r"(addr));
}
__device__ __forceinline__ void mma_f16(float* c, const uint32_t* a,
                                        uint32_t b0, uint32_t b1) {
    asm volatile(
        "mma.sync.aligned.m16n8k16.row.col.f32.f16.f16.f32 "
        "{%0,%1,%2,%3}, {%4,%5,%6,%7}, {%8,%9}, {%0,%1,%2,%3};"
        : "+f"(c[0]), "+f"(c[1]), "+f"(c[2]), "+f"(c[3])
        : "r"(a[0]), "r"(a[1]), "r"(a[2]), "r"(a[3]), "r"(b0), "r"(b1));
}
__device__ __forceinline__ uint32_t pack_h2(float x, float y) {
    __half2 h = __floats2half2_rn(x, y);
    return *(uint32_t*)&h;
}

// ---------------------------------------------------------------------------
// fp32 -> fp16 elementwise (4 elems/thread)
// ---------------------------------------------------------------------------
__global__ __launch_bounds__(256)
void conv_h(const float* __restrict__ in, __half* __restrict__ out)
{
    const size_t i = ((size_t)blockIdx.x * 256 + threadIdx.x) * 4;
    float4 v = *(const float4*)&in[i];
    __half2 a = __floats2half2_rn(v.x, v.y);
    __half2 b = __floats2half2_rn(v.z, v.w);
    *(__half2*)&out[i]     = a;
    *(__half2*)&out[i + 2] = b;
}

// ---------------------------------------------------------------------------
// Weight transpose + fp16 convert.  in block z: [R,C] row-major fp32.
// out row n = z*C + c (length R): out[n*R + r] = in[z][r][c].
// ---------------------------------------------------------------------------
__global__ __launch_bounds__(256)
void wconv(const float* __restrict__ in, __half* __restrict__ oh, int R, int C)
{
    __shared__ float tile[32][33];
    const int bz = blockIdx.z;
    const float* ip = in + (size_t)bz * R * C;
    const int r0 = blockIdx.y * 32, c0 = blockIdx.x * 32;
    const int tx = threadIdx.x & 31;
    const int ty = threadIdx.x >> 5;

    #pragma unroll
    for (int i = 0; i < 32; i += 8)
        tile[ty + i][tx] = ip[(size_t)(r0 + ty + i) * C + c0 + tx];
    __syncthreads();

    #pragma unroll
    for (int i = 0; i < 32; i += 8) {
        float x = tile[tx][ty + i];
        size_t o = ((size_t)bz * C + c0 + ty + i) * R + r0 + tx;
        oh[o] = __float2half_rn(x);
    }
}

// 3-way wconv for QKV triples ([H,D,R] each, H=16 blocks of 1024x64)
__global__ __launch_bounds__(256)
void wconv3(const float* __restrict__ wq, const float* __restrict__ wk,
            const float* __restrict__ wv, __half* __restrict__ oh)
{
    __shared__ float tile[32][33];
    const int z   = blockIdx.z;            // 0..47
    const int sel = z >> 4;
    const int bz  = z & 15;
    const float* in = (sel == 0) ? wq : (sel == 1) ? wk : wv;
    __half* out = oh + (size_t)sel * WME;
    const int R = 1024, C = 64;
    const float* ip = in + (size_t)bz * R * C;
    const int r0 = blockIdx.y * 32, c0 = blockIdx.x * 32;
    const int tx = threadIdx.x & 31;
    const int ty = threadIdx.x >> 5;

    #pragma unroll
    for (int i = 0; i < 32; i += 8)
        tile[ty + i][tx] = ip[(size_t)(r0 + ty + i) * C + c0 + tx];
    __syncthreads();

    #pragma unroll
    for (int i = 0; i < 32; i += 8) {
        float x = tile[tx][ty + i];
        size_t o = ((size_t)bz * C + c0 + ty + i) * R + r0 + tx;
        out[o] = __float2half_rn(x);
    }
}

// ---------------------------------------------------------------------------
// Tensor-core GEMM (fp16 in, fp32 accumulate).  All operands fp16 in HBM.
// C = A[M,K] * W[N,K]^T (+bias) (+resid) (relu?)
// OMODE 0: fp32 row-major out.  1: fused-QKV fp16 out in [3][B,H,S,R]
//          (A/bias selected per 1024-column group).  2: fp16 row-major out.
// CTA 128x128, BK=32, double-buffered, all staging via cp.async.
// ---------------------------------------------------------------------------
#define PITCH 80
#define OFF_W  10240
#define BUFSZ  20480
#define GSMEM  (2*BUFSZ)

template<int OMODE, bool RESID, bool RELU>
__global__ __launch_bounds__(256)
void tgemm(const __half* __restrict__ A0, const __half* __restrict__ A1,
           const __half* __restrict__ A2, const __half* __restrict__ W,
           const float* __restrict__ b0, const float* __restrict__ b1,
           const float* __restrict__ b2, const float* __restrict__ resid,
           void* __restrict__ Cout, int M, int N, int K)
{
    extern __shared__ char smem[];
    const uint32_t sb = smem_to_u32(smem);

    const int t    = threadIdx.x;
    const int lane = t & 31;
    const int wid  = t >> 5;
    const int wm   = wid & 3;
    const int wn   = wid >> 2;
    const int m0   = blockIdx.y * 128;
    const int n0   = blockIdx.x * 128;
    const int nch  = K >> 5;

    const int which = (OMODE == 1) ? (n0 >> 10) : 0;
    const __half* A   = (which == 0) ? A0 : (which == 1) ? A1 : A2;
    const float* bias = (which == 0) ? b0 : (which == 1) ? b1 : b2;

    // A staging: row t>>1, 32B half (t&1)
    const uint32_t aDst = (uint32_t)(t >> 1) * PITCH + (t & 1) * 32;
    const __half*  aSrcBase = A + (size_t)(m0 + (t >> 1)) * K + (t & 1) * 16;
    // W staging: 2 16B chunks per thread
    const int q0r = (2 * t) >> 2,     q0c = (2 * t) & 3;
    const int q1r = (2 * t + 1) >> 2, q1c = (2 * t + 1) & 3;

    float acc[2][8][4];
    #pragma unroll
    for (int a = 0; a < 2; a++)
        #pragma unroll
        for (int b = 0; b < 8; b++)
            #pragma unroll
            for (int d = 0; d < 4; d++) acc[a][b][d] = 0.f;

    auto loadAW = [&](int k0, uint32_t bufo) {
        cp_async16(sb + bufo + aDst,      aSrcBase + k0);
        cp_async16(sb + bufo + aDst + 16, aSrcBase + k0 + 8);
        cp_async16(sb + bufo + OFF_W + q0r * PITCH + q0c * 16,
                   W + (size_t)(n0 + q0r) * K + k0 + q0c * 8);
        cp_async16(sb + bufo + OFF_W + q1r * PITCH + q1c * 16,
                   W + (size_t)(n0 + q1r) * K + k0 + q1c * 8);
        CP_COMMIT();
    };

    const uint32_t aBase = sb + (uint32_t)(wm * 32 + (lane & 15)) * PITCH + (lane >> 4) * 16;
    const uint32_t wBase = sb + OFF_W
        + (uint32_t)(wn * 64 + ((lane >> 4) << 3) + (lane & 7)) * PITCH
        + ((lane >> 3) & 1) * 16;

    auto compute = [&](uint32_t bufo) {
        #pragma unroll
        for (int ks = 0; ks < 2; ks++) {
            uint32_t ah[2][4];
            #pragma unroll
            for (int mt = 0; mt < 2; mt++)
                ldm_x4(ah[mt], aBase + bufo + mt * (16*PITCH) + ks * 32);
            #pragma unroll
            for (int ng = 0; ng < 2; ng++) {
                uint32_t bh[8];
                #pragma unroll
                for (int p = 0; p < 2; p++)
                    ldm_x4(bh + p*4, wBase + bufo + (ng*2 + p) * (16*PITCH) + ks * 32);
                #pragma unroll
                for (int nt = 0; nt < 4; nt++)
                    #pragma unroll
                    for (int mt = 0; mt < 2; mt++)
                        mma_f16(acc[mt][ng*4 + nt], ah[mt], bh[nt*2], bh[nt*2+1]);
            }
        }
    };

    loadAW(0, 0);
    CP_WAIT0();
    __syncthreads();

    for (int c = 0; c < nch; c++) {
        const uint32_t bufo = (c & 1) * BUFSZ;
        const bool hasNext = (c + 1 < nch);
        if (hasNext) loadAW((c + 1) << 5, BUFSZ - bufo);
        compute(bufo);
        if (hasNext) CP_WAIT0();
        __syncthreads();
    }

    // ---- epilogue ----
    #pragma unroll
    for (int mt = 0; mt < 2; mt++) {
        const int m = m0 + wm * 32 + mt * 16 + (lane >> 2);
        #pragma unroll
        for (int j = 0; j < 8; j++) {
            const int n = n0 + wn * 64 + j * 8 + (lane & 3) * 2;
            const int nb = (OMODE == 1) ? (n & 1023) : n;
            float2 v0 = make_float2(acc[mt][j][0], acc[mt][j][1]);
            float2 v1 = make_float2(acc[mt][j][2], acc[mt][j][3]);
            float2 b2v = *(const float2*)&bias[nb];
            v0.x += b2v.x; v0.y += b2v.y;
            v1.x += b2v.x; v1.y += b2v.y;
            if (RESID) {
                float2 r0 = *(const float2*)&resid[(size_t)m * N + n];
                float2 r1 = *(const float2*)&resid[(size_t)(m + 8) * N + n];
                v0.x += r0.x; v0.y += r0.y;
                v1.x += r1.x; v1.y += r1.y;
            }
            if (RELU) {
                v0.x = fmaxf(v0.x, 0.f); v0.y = fmaxf(v0.y, 0.f);
                v1.x = fmaxf(v1.x, 0.f); v1.y = fmaxf(v1.y, 0.f);
            }
            if (OMODE == 0) {
                float* C = (float*)Cout;
                *(float2*)&C[(size_t)m * N + n]       = v0;
                *(float2*)&C[(size_t)(m + 8) * N + n] = v1;
            } else if (OMODE == 2) {
                __half* C = (__half*)Cout;
                *(__half2*)&C[(size_t)m * N + n]       = __floats2half2_rn(v0.x, v0.y);
                *(__half2*)&C[(size_t)(m + 8) * N + n] = __floats2half2_rn(v1.x, v1.y);
            } else {
                __half* C = (__half*)Cout;
                const int h = nb >> 6, r = nb & 63;
                size_t o0 = (size_t)which * BHSR
                          + ((size_t)((m >> 10) * NHEAD + h) * SEQ + (m & (SEQ-1))) * DRED + r;
                size_t o1 = (size_t)which * BHSR
                          + ((size_t)(((m+8) >> 10) * NHEAD + h) * SEQ + ((m+8) & (SEQ-1))) * DRED + r;
                *(__half2*)&C[o0] = __floats2half2_rn(v0.x, v0.y);
                *(__half2*)&C[o1] = __floats2half2_rn(v1.x, v1.y);
            }
        }
    }
}

// ---------------------------------------------------------------------------
// Tensor-core flash attention (fp16 in/out, exact online softmax).
// Q,K,V: [B,H,S,R] fp16 (q = qkv+0, k = +BHSR, v = +2*BHSR).
// Out: fp16 [B*S, H*R].  Grid (S/128, B*H), 256 threads.
// ---------------------------------------------------------------------------
#define APITCH 144
#define SQ_OFF 0
#define SK_OFF 18432
#define SV_OFF 36864
#define ASMEM  55296

__global__ __launch_bounds__(256)
void attn_tc(const __half* __restrict__ QKV, __half* __restrict__ Out)
{
    extern __shared__ char sm[];
    const uint32_t sb = smem_to_u32(sm);

    const int t    = threadIdx.x;
    const int lane = t & 31;
    const int w    = t >> 5;
    const int bh   = blockIdx.y;
    const int b    = bh >> 4;
    const int h    = bh & 15;
    const int q0   = blockIdx.x * 128;

    const size_t base = (size_t)bh * SEQ * DRED;
    const __half* Qb = QKV + base;
    const __half* Kb = QKV + BHSR + base;
    const __half* Vb = QKV + 2 * BHSR + base;

    // staging: thread t -> row t>>1, 64B half (t&1); 4 cp.async16
    const int lrow  = t >> 1;
    const int lhalf = t & 1;
    auto stage = [&](const __half* src, uint32_t dst) {
        const __half* g = src + (size_t)lrow * DRED + lhalf * 32;
        uint32_t d = sb + dst + (uint32_t)lrow * APITCH + lhalf * 64;
        cp_async16(d,      g);
        cp_async16(d + 16, g + 8);
        cp_async16(d + 32, g + 16);
        cp_async16(d + 48, g + 24);
    };

    stage(Qb + (size_t)q0 * DRED, SQ_OFF);
    CP_COMMIT();

    const uint32_t aOff = (uint32_t)(w * 16 + (lane & 15)) * APITCH + (lane >> 4) * 16;
    const uint32_t kRow = ((lane >> 4) << 3) + (lane & 7);
    const uint32_t kCol = ((lane >> 3) & 1) * 16;

    float S[16][4];
    float O[8][4];
    float m0 = -1e30f, m1 = -1e30f, l0 = 0.f, l1 = 0.f;
    #pragma unroll
    for (int j = 0; j < 8; j++)
        #pragma unroll
        for (int d = 0; d < 4; d++) O[j][d] = 0.f;

    for (int kt = 0; kt < SEQ / 128; kt++) {
        __syncthreads();
        stage(Kb + (size_t)(kt * 128) * DRED, SK_OFF);
        stage(Vb + (size_t)(kt * 128) * DRED, SV_OFF);
        CP_COMMIT();
        CP_WAIT0();
        __syncthreads();

        // ---- S = Q K^T ----
        #pragma unroll
        for (int j = 0; j < 16; j++) {
            S[j][0] = 0.f; S[j][1] = 0.f; S[j][2] = 0.f; S[j][3] = 0.f;
        }
        #pragma unroll
        for (int ks = 0; ks < 4; ks++) {
            uint32_t qh[4];
            ldm_x4(qh, sb + SQ_OFF + aOff + ks * 32);
            #pragma unroll
            for (int np = 0; np < 8; np++) {
                uint32_t off = (uint32_t)(np * 16 + kRow) * APITCH + kCol + ks * 32;
                uint32_t bh4[4];
                ldm_x4(bh4, sb + SK_OFF + off);
                #pragma unroll
                for (int nt = 0; nt < 2; nt++)
                    mma_f16(S[np * 2 + nt], qh, bh4[nt*2], bh4[nt*2+1]);
            }
        }

        // ---- online softmax ----
        float mx0 = -1e30f, mx1 = -1e30f;
        #pragma unroll
        for (int j = 0; j < 16; j++) {
            S[j][0] *= 0.125f; S[j][1] *= 0.125f;
            S[j][2] *= 0.125f; S[j][3] *= 0.125f;
            mx0 = fmaxf(mx0, fmaxf(S[j][0], S[j][1]));
            mx1 = fmaxf(mx1, fmaxf(S[j][2], S[j][3]));
        }
        mx0 = fmaxf(mx0, __shfl_xor_sync(0xffffffffu, mx0, 1));
        mx0 = fmaxf(mx0, __shfl_xor_sync(0xffffffffu, mx0, 2));
        mx1 = fmaxf(mx1, __shfl_xor_sync(0xffffffffu, mx1, 1));
        mx1 = fmaxf(mx1, __shfl_xor_sync(0xffffffffu, mx1, 2));
        float mn0 = fmaxf(m0, mx0), mn1 = fmaxf(m1, mx1);
        float a0 = __expf(m0 - mn0), a1 = __expf(m1 - mn1);
        m0 = mn0; m1 = mn1;
        float rs0 = 0.f, rs1 = 0.f;
        #pragma unroll
        for (int j = 0; j < 16; j++) {
            float p0 = __expf(S[j][0] - mn0); S[j][0] = p0; rs0 += p0;
            float p1 = __expf(S[j][1] - mn0); S[j][1] = p1; rs0 += p1;
            float p2 = __expf(S[j][2] - mn1); S[j][2] = p2; rs1 += p2;
            float p3 = __expf(S[j][3] - mn1); S[j][3] = p3; rs1 += p3;
        }
        l0 = l0 * a0 + rs0;
        l1 = l1 * a1 + rs1;
        #pragma unroll
        for (int j = 0; j < 8; j++) {
            O[j][0] *= a0; O[j][1] *= a0;
            O[j][2] *= a1; O[j][3] *= a1;
        }

        // ---- O += P V ----
        #pragma unroll
        for (int ks = 0; ks < 8; ks++) {
            uint32_t ah[4];
            ah[0] = pack_h2(S[2*ks][0],   S[2*ks][1]);
            ah[1] = pack_h2(S[2*ks][2],   S[2*ks][3]);
            ah[2] = pack_h2(S[2*ks+1][0], S[2*ks+1][1]);
            ah[3] = pack_h2(S[2*ks+1][2], S[2*ks+1][3]);
            #pragma unroll
            for (int np = 0; np < 4; np++) {
                uint32_t off = (uint32_t)(ks * 16 + ((lane >> 3) & 1) * 8 + (lane & 7)) * APITCH
                             + (np * 16 + (lane >> 4) * 8) * 2;
                uint32_t bh4[4];
                ldm_x4_t(bh4, sb + SV_OFF + off);
                #pragma unroll
                for (int nt = 0; nt < 2; nt++)
                    mma_f16(O[np * 2 + nt], ah, bh4[nt*2], bh4[nt*2+1]);
            }
        }
    }

    // ---- finalize ----
    l0 += __shfl_xor_sync(0xffffffffu, l0, 1);
    l0 += __shfl_xor_sync(0xffffffffu, l0, 2);
    l1 += __shfl_xor_sync(0xffffffffu, l1, 1);
    l1 += __shfl_xor_sync(0xffffffffu, l1, 2);
    const float inv0 = 1.f / l0, inv1 = 1.f / l1;

    const int r0 = q0 + w * 16 + (lane >> 2);
    const size_t tok0 = (size_t)b * SEQ + r0;
    const size_t tok1 = tok0 + 8;
    #pragma unroll
    for (int ng = 0; ng < 8; ng++) {
        const int col = h * DRED + ng * 8 + (lane & 3) * 2;
        *(__half2*)&Out[tok0 * DEMB + col] = __floats2half2_rn(O[ng][0] * inv0, O[ng][1] * inv0);
        *(__half2*)&Out[tok1 * DEMB + col] = __floats2half2_rn(O[ng][2] * inv1, O[ng][3] * inv1);
    }
}

// ---------------------------------------------------------------------------
// LayerNorm over rows of 1024, eps = 1e-3; optional dual fp16 write
// ---------------------------------------------------------------------------
template<bool DUALH>
__global__ __launch_bounds__(256)
void ln_kernel(const float* __restrict__ in, const float* __restrict__ gam,
               const float* __restrict__ bet, float* __restrict__ out,
               __half* __restrict__ outh)
{
    __shared__ float red[16];
    const int row = blockIdx.x;
    const int t   = threadIdx.x;
    const float* p = in + (size_t)row * DEMB;

    float4 v = *(const float4*)&p[t * 4];
    float s  = v.x + v.y + v.z + v.w;
    float ss = v.x * v.x + v.y * v.y + v.z * v.z + v.w * v.w;
    #pragma unroll
    for (int o = 16; o >= 1; o >>= 1) {
        s  += __shfl_xor_sync(0xffffffffu, s, o);
        ss += __shfl_xor_sync(0xffffffffu, ss, o);
    }
    if ((t & 31) == 0) { red[t >> 5] = s; red[8 + (t >> 5)] = ss; }
    __syncthreads();
    s = 0.f; ss = 0.f;
    #pragma unroll
    for (int i = 0; i < 8; i++) { s += red[i]; ss += red[8 + i]; }

    float mean = s * (1.f / DEMB);
    float var  = ss * (1.f / DEMB) - mean * mean;
    float r    = rsqrtf(var + 1e-3f);

    float4 g4 = *(const float4*)&gam[t * 4];
    float4 b4 = *(const float4*)&bet[t * 4];
    float4 o;
    o.x = (v.x - mean) * r * g4.x + b4.x;
    o.y = (v.y - mean) * r * g4.y + b4.y;
    o.z = (v.z - mean) * r * g4.z + b4.z;
    o.w = (v.w - mean) * r * g4.w + b4.w;
    *(float4*)&out[(size_t)row * DEMB + t * 4] = o;
    if (DUALH) {
        *(__half2*)&outh[(size_t)row * DEMB + t * 4]     = __floats2half2_rn(o.x, o.y);
        *(__half2*)&outh[(size_t)row * DEMB + t * 4 + 2] = __floats2half2_rn(o.z, o.w);
    }
}

// ---------------------------------------------------------------------------
// Launch
// ---------------------------------------------------------------------------
extern "C" void kernel_launch(void* const* d_in, const int* in_sizes, int n_in,
                              void* d_out, int out_size)
{
    const float* x      = (const float*)d_in[0];
    const float* ctx    = (const float*)d_in[1];
    const float* sa_wq  = (const float*)d_in[2];
    const float* sa_bq  = (const float*)d_in[3];
    const float* sa_wk  = (const float*)d_in[4];
    const float* sa_bk  = (const float*)d_in[5];
    const float* sa_wv  = (const float*)d_in[6];
    const float* sa_bv  = (const float*)d_in[7];
    const float* sa_wo  = (const float*)d_in[8];
    const float* sa_bo  = (const float*)d_in[9];
    const float* ca_wq  = (const float*)d_in[10];
    const float* ca_bq  = (const float*)d_in[11];
    const float* ca_wk  = (const float*)d_in[12];
    const float* ca_bk  = (const float*)d_in[13];
    const float* ca_wv  = (const float*)d_in[14];
    const float* ca_bv  = (const float*)d_in[15];
    const float* ca_wo  = (const float*)d_in[16];
    const float* ca_bo  = (const float*)d_in[17];
    const float* ln1_g  = (const float*)d_in[18];
    const float* ln1_b  = (const float*)d_in[19];
    const float* ln2_g  = (const float*)d_in[20];
    const float* ln2_b  = (const float*)d_in[21];
    const float* ln3_g  = (const float*)d_in[22];
    const float* ln3_b  = (const float*)d_in[23];
    const float* ffn_w1 = (const float*)d_in[24];
    const float* ffn_b1 = (const float*)d_in[25];
    const float* ffn_w2 = (const float*)d_in[26];
    const float* ffn_b2 = (const float*)d_in[27];
    float* out = (float*)d_out;

    float *res, *ln1, *ln2;
    __half *xh, *ctxh, *ln1h, *ln2h, *atth, *ffnh, *qkvh, *wh;
    cudaGetSymbolAddress((void**)&res,  g_res);
    cudaGetSymbolAddress((void**)&ln1,  g_ln1);
    cudaGetSymbolAddress((void**)&ln2,  g_ln2);
    cudaGetSymbolAddress((void**)&xh,   g_xh);
    cudaGetSymbolAddress((void**)&ctxh, g_ctxh);
    cudaGetSymbolAddress((void**)&ln1h, g_ln1h);
    cudaGetSymbolAddress((void**)&ln2h, g_ln2h);
    cudaGetSymbolAddress((void**)&atth, g_atth);
    cudaGetSymbolAddress((void**)&ffnh, g_ffnh);
    cudaGetSymbolAddress((void**)&qkvh, g_qkvh);
    cudaGetSymbolAddress((void**)&wh,   g_wh);

    cudaFuncSetAttribute(tgemm<1, false, false>, cudaFuncAttributeMaxDynamicSharedMemorySize, GSMEM);
    cudaFuncSetAttribute(tgemm<0, true,  false>, cudaFuncAttributeMaxDynamicSharedMemorySize, GSMEM);
    cudaFuncSetAttribute(tgemm<2, false, true >, cudaFuncAttributeMaxDynamicSharedMemorySize, GSMEM);
    cudaFuncSetAttribute(attn_tc, cudaFuncAttributeMaxDynamicSharedMemorySize, ASMEM);

    // ---- input conversions ----
    conv_h<<<NTOK * DEMB / 1024, 256>>>(x,   xh);
    conv_h<<<NTOK * DEMB / 1024, 256>>>(ctx, ctxh);

    // ---- weight conversions ----
    dim3 tp3(2, 32, 48);
    wconv3<<<tp3, 256>>>(sa_wq, sa_wk, sa_wv, wh + (size_t)0*WME);
    wconv3<<<tp3, 256>>>(ca_wq, ca_wk, ca_wv, wh + (size_t)4*WME);
    dim3 tpO(32, 32, 1);
    wconv<<<tpO, 256>>>(sa_wo, wh + (size_t)3*WME, 1024, 1024);
    wconv<<<tpO, 256>>>(ca_wo, wh + (size_t)7*WME, 1024, 1024);
    dim3 tpF1(128, 32, 1);
    wconv<<<tpF1, 256>>>(ffn_w1, wh + (size_t)8*WME,  1024, 4096);
    dim3 tpF2(32, 128, 1);
    wconv<<<tpF2, 256>>>(ffn_w2, wh + (size_t)12*WME, 4096, 1024);

    dim3 gQKV(3 * DEMB / 128, NTOK / 128);   // (24, 32)
    dim3 gProj(DEMB / 128, NTOK / 128);      // (8, 32)
    dim3 gFfn1(DFFN / 128, NTOK / 128);      // (32, 32)
    dim3 gAttn(SEQ / 128, BQ * NHEAD);       // (8, 64)

    // ---- self attention ----
    tgemm<1, false, false><<<gQKV, 256, GSMEM>>>(xh, xh, xh, wh + (size_t)0*WME,
        sa_bq, sa_bk, sa_bv, nullptr, qkvh, NTOK, 3*DEMB, DEMB);
    attn_tc<<<gAttn, 256, ASMEM>>>(qkvh, atth);
    tgemm<0, true, false><<<gProj, 256, GSMEM>>>(atth, atth, atth, wh + (size_t)3*WME,
        sa_bo, sa_bo, sa_bo, x, res, NTOK, DEMB, DEMB);
    ln_kernel<true><<<NTOK, 256>>>(res, ln1_g, ln1_b, ln1, ln1h);

    // ---- cross attention ----
    tgemm<1, false, false><<<gQKV, 256, GSMEM>>>(ln1h, ctxh, ctxh, wh + (size_t)4*WME,
        ca_bq, ca_bk, ca_bv, nullptr, qkvh, NTOK, 3*DEMB, DEMB);
    attn_tc<<<gAttn, 256, ASMEM>>>(qkvh, atth);
    tgemm<0, true, false><<<gProj, 256, GSMEM>>>(atth, atth, atth, wh + (size_t)7*WME,
        ca_bo, ca_bo, ca_bo, ln1, res, NTOK, DEMB, DEMB);
    ln_kernel<true><<<NTOK, 256>>>(res, ln2_g, ln2_b, ln2, ln2h);

    // ---- FFN ----
    tgemm<2, false, true><<<gFfn1, 256, GSMEM>>>(ln2h, ln2h, ln2h, wh + (size_t)8*WME,
        ffn_b1, ffn_b1, ffn_b1, nullptr, ffnh, NTOK, DFFN, DEMB);
    tgemm<0, true, false><<<gProj, 256, GSMEM>>>(ffnh, ffnh, ffnh, wh + (size_t)12*WME,
        ffn_b2, ffn_b2, ffn_b2, ln2, res, NTOK, DEMB, DFFN);
    ln_kernel<false><<<NTOK, 256>>>(res, ln3_g, ln3_b, out, nullptr);
}